// round 8
// baseline (speedup 1.0000x reference)
#include <cuda_runtime.h>
#include <cstdint>

// Two-simplicial attention, B=2, S=2048, H=4, D=64, W1=W2=64 (A=C=65).
// 1 position per CTA, 256 threads, 2 CTAs/SM.
// R8 = R6 + row-major k2 (no transpose; vector B-loads) + k2/v1/v2 via cp.async.bulk.

constexpr int Bc = 2, Sc = 2048, Hc = 4, Dc = 64;
constexpr float SCALE_F = 0.125f;
constexpr int NT = 256;

// ---- smem layout (floats) ----
constexpr int OFF_MBAR = 0;                    // 8 B mbarrier
constexpr int OFF_K1Q  = 4;                    // [65][64] q-folded k1
constexpr int OFF_K2   = OFF_K1Q + 65 * 64;    // [65][68] k2 row-major, stride 68
constexpr int OFF_V1   = OFF_K2 + 65 * 68;     // [65][64]
constexpr int OFF_V2   = OFF_V1 + 65 * 64;     // [65][64]
constexpr int OFF_W    = OFF_V2 + 65 * 64;     // [72][68]
constexpr int OFF_NP   = OFF_W + 72 * 68;      // [8][64]
constexpr int OFF_DEN  = OFF_NP + 8 * 64;      // [8]
constexpr int SMEM_FLOATS = OFF_DEN + 8;
constexpr int SMEM_BYTES = SMEM_FLOATS * 4;    // ~89.3 KB -> 2 CTAs/SM

typedef unsigned long long ull;

__device__ __forceinline__ void ffma2(ull& acc, ull a, ull b) {
    asm("fma.rn.f32x2 %0, %1, %2, %0;" : "+l"(acc) : "l"(a), "l"(b));
}
__device__ __forceinline__ ull pack2(float lo, float hi) {
    ull r;
    asm("mov.b64 %0, {%1, %2};" : "=l"(r) : "f"(lo), "f"(hi));
    return r;
}
__device__ __forceinline__ float2 unpack2(ull v) {
    float2 f;
    asm("mov.b64 {%0, %1}, %2;" : "=f"(f.x), "=f"(f.y) : "l"(v));
    return f;
}
__device__ __forceinline__ uint32_t smem_u32(const void* p) {
    uint32_t a;
    asm("{ .reg .u64 t; cvta.to.shared.u64 t, %1; cvt.u32.u64 %0, t; }"
        : "=r"(a) : "l"(p));
    return a;
}
__device__ __forceinline__ void mbar_init(uint32_t mbar, uint32_t cnt) {
    asm volatile("mbarrier.init.shared.b64 [%0], %1;" :: "r"(mbar), "r"(cnt) : "memory");
}
__device__ __forceinline__ void mbar_expect_tx(uint32_t mbar, uint32_t bytes) {
    asm volatile("mbarrier.arrive.expect_tx.shared.b64 _, [%0], %1;"
                 :: "r"(mbar), "r"(bytes) : "memory");
}
__device__ __forceinline__ void bulk_cp(uint32_t dst, const void* src,
                                        uint32_t bytes, uint32_t mbar) {
    asm volatile(
        "cp.async.bulk.shared::cluster.global.mbarrier::complete_tx::bytes "
        "[%0], [%1], %2, [%3];"
        :: "r"(dst), "l"(src), "r"(bytes), "r"(mbar) : "memory");
}
__device__ __forceinline__ void mbar_wait(uint32_t mbar, uint32_t parity) {
    asm volatile(
        "{\n\t"
        ".reg .pred P;\n\t"
        "WAIT_%=:\n\t"
        "mbarrier.try_wait.parity.acquire.cta.shared::cta.b64 P, [%0], %1;\n\t"
        "@P bra WAIT_DONE_%=;\n\t"
        "bra.uni WAIT_%=;\n\t"
        "WAIT_DONE_%=:\n\t"
        "}"
        :: "r"(mbar), "r"(parity) : "memory");
}

__global__ void __launch_bounds__(NT, 2)
tsa_kernel(const float* __restrict__ q,
           const float* __restrict__ k1,
           const float* __restrict__ k2,
           const float* __restrict__ v1,
           const float* __restrict__ v2,
           float* __restrict__ out) {
    extern __shared__ float sm[];
    const int tid = threadIdx.x;
    const int bid = blockIdx.x;
    const int h = bid & 3;
    const int s = (bid >> 2) & 2047;
    const int b = bid >> 13;

    const uint32_t smb = smem_u32(sm);
    const uint32_t mbar = smb + OFF_MBAR * 4;

    if (tid == 0) mbar_init(mbar, 1);
    __syncthreads();   // mbarrier init visible before any complete_tx

    // ---- async k2/v1/v2 window copies (195 rows x 256B) ----
    if (tid == 0) mbar_expect_tx(mbar, 195 * 256);
    if (tid < 195) {
        int which = tid / 65;             // 0=k2, 1=v1, 2=v2
        int r = tid - which * 65;
        int g = s - 64 + r; if (g < 0) g = 0;
        const float* basep = (which == 0) ? k2 : (which == 1) ? v1 : v2;
        int dstoff = (which == 0) ? (OFF_K2 + r * 68)
                   : (which == 1) ? (OFF_V1 + r * 64)
                                  : (OFF_V2 + r * 64);
        bulk_cp(smb + 4 * dstoff, basep + ((b * Sc + g) * Hc + h) * Dc, 256, mbar);
    }

    // ---- zero W cols 64..67 for rows 65..71 (read in phase 4, never written) ----
    if (tid >= 224 && tid < 252) {
        int t = tid - 224;
        sm[OFF_W + (65 + (t >> 2)) * 68 + 64 + (t & 3)] = 0.0f;
    }

    // ================= stage A: q + k1 load, fold =================
    const int qb = ((b * Sc + s) * Hc + h) * Dc;
    const int dq = tid & 15;
    const float4 qv = *(const float4*)&q[qb + dq * 4];

    for (int i = tid; i < 65 * 16; i += NT) {
        int r = i >> 4;
        int g = s - 64 + r; if (g < 0) g = 0;
        int off = ((b * Sc + g) * Hc + h) * Dc + dq * 4;
        float4 kv = *(const float4*)&k1[off];
        kv.x *= qv.x; kv.y *= qv.y; kv.z *= qv.z; kv.w *= qv.w;
        *(float4*)&sm[OFF_K1Q + r * 64 + dq * 4] = kv;
    }
    __syncthreads();       // k1q + W pads visible to all
    mbar_wait(mbar, 0);    // k2/v1/v2 resident

    // ================= phase 3: scores + exp =================
    const int wid = tid >> 5, lane = tid & 31;
    const int a0 = wid * 9;
    const int amin = 64 - s;

    int rowi[9];
#pragma unroll
    for (int i = 0; i < 9; i++) {
        int r = a0 + i;
        rowi[i] = (r > 64) ? 64 : r;
    }

    ull acc[9][2];
#pragma unroll
    for (int i = 0; i < 9; i++) { acc[i][0] = 0ull; acc[i][1] = 0ull; }

    const float* b0 = &sm[OFF_K2 + lane * 68];          // c = lane
    const float* b1 = &sm[OFF_K2 + (lane + 32) * 68];   // c = lane + 32

#pragma unroll 4
    for (int dqi = 0; dqi < 16; dqi++) {
        int d0 = dqi * 4;
        ulonglong2 kc0 = *(const ulonglong2*)(b0 + d0);  // .x=(d0,d1) .y=(d2,d3) @ c=lane
        ulonglong2 kc1 = *(const ulonglong2*)(b1 + d0);  //   "         @ c=lane+32
#pragma unroll
        for (int i = 0; i < 9; i++) {
            ulonglong2 a4 = *(const ulonglong2*)&sm[OFF_K1Q + rowi[i] * 64 + d0];
            ffma2(acc[i][0], a4.x, kc0.x);
            ffma2(acc[i][1], a4.x, kc1.x);
            ffma2(acc[i][0], a4.y, kc0.y);
            ffma2(acc[i][1], a4.y, kc1.y);
        }
    }

    float dloc = 0.0f;
#pragma unroll
    for (int i = 0; i < 9; i++) {
        int a = a0 + i;
        bool av = (a < 65) && (a >= amin);
#pragma unroll
        for (int jc = 0; jc < 2; jc++) {
            int c = lane + 32 * jc;
            float2 t = unpack2(acc[i][jc]);
            float sc = (t.x + t.y) * SCALE_F;
            float wv = 0.0f;
            if (av && c >= amin) { wv = __expf(sc); dloc += wv; }
            sm[OFF_W + a * 68 + c] = wv;   // rows >= 65 get zeros
        }
    }
    // tail column c = 64 (always >= amin); zero pad cols 65..67
    {
        float2 kf2 = *(const float2*)&sm[OFF_K2 + 64 * 68 + lane * 2];
#pragma unroll
        for (int i = 0; i < 9; i++) {
            float2 kf = *(const float2*)&sm[OFF_K1Q + rowi[i] * 64 + lane * 2];
            float t = kf.x * kf2.x + kf.y * kf2.y;
#pragma unroll
            for (int o = 16; o; o >>= 1) t += __shfl_xor_sync(0xFFFFFFFFu, t, o);
            if (lane == 0) {
                int a = a0 + i;
                if (a < 65) {
                    float wv = (a >= amin) ? __expf(t * SCALE_F) : 0.0f;
                    dloc += wv;
                    sm[OFF_W + a * 68 + 64] = wv;
                    sm[OFF_W + a * 68 + 65] = 0.0f;
                    sm[OFF_W + a * 68 + 66] = 0.0f;
                    sm[OFF_W + a * 68 + 67] = 0.0f;
                }
            }
        }
    }
#pragma unroll
    for (int o = 16; o; o >>= 1) dloc += __shfl_xor_sync(0xFFFFFFFFu, dloc, o);
    if (lane == 0) sm[OFF_DEN + wid] = dloc;
    __syncwarp();   // each warp reads only its own W rows below

    // ================= phase 4: num = sum_a v1[a] * (W[a,:] @ V2) =================
    ull tmp[9][2];
#pragma unroll
    for (int i = 0; i < 9; i++) { tmp[i][0] = 0ull; tmp[i][1] = 0ull; }

#pragma unroll 4
    for (int cq = 0; cq < 16; cq++) {
        int c = cq * 4;
        float va0 = sm[OFF_V2 + (c    ) * 64 + lane];
        float va1 = sm[OFF_V2 + (c + 1) * 64 + lane];
        float va2 = sm[OFF_V2 + (c + 2) * 64 + lane];
        float va3 = sm[OFF_V2 + (c + 3) * 64 + lane];
        float vb0 = sm[OFF_V2 + (c    ) * 64 + lane + 32];
        float vb1 = sm[OFF_V2 + (c + 1) * 64 + lane + 32];
        float vb2 = sm[OFF_V2 + (c + 2) * 64 + lane + 32];
        float vb3 = sm[OFF_V2 + (c + 3) * 64 + lane + 32];
        ull vp0 = pack2(va0, va1), vp1 = pack2(va2, va3);
        ull vq0 = pack2(vb0, vb1), vq1 = pack2(vb2, vb3);
#pragma unroll
        for (int i = 0; i < 9; i++) {
            ulonglong2 wq = *(const ulonglong2*)&sm[OFF_W + (a0 + i) * 68 + c];
            ffma2(tmp[i][0], wq.x, vp0);
            ffma2(tmp[i][1], wq.x, vq0);
            ffma2(tmp[i][0], wq.y, vp1);
            ffma2(tmp[i][1], wq.y, vq1);
        }
    }
    // tail c = 64 + v1 contraction
    float v64a = sm[OFF_V2 + 64 * 64 + lane];
    float v64b = sm[OFF_V2 + 64 * 64 + lane + 32];
    float ns0 = 0.0f, ns1 = 0.0f;
#pragma unroll
    for (int i = 0; i < 9; i++) {
        float w64 = sm[OFF_W + (a0 + i) * 68 + 64];
        float2 t0 = unpack2(tmp[i][0]);
        float2 t1 = unpack2(tmp[i][1]);
        float ta = t0.x + t0.y + w64 * v64a;
        float tb = t1.x + t1.y + w64 * v64b;
        ta *= sm[OFF_V1 + rowi[i] * 64 + lane];        // invalid rows: all-zero W
        tb *= sm[OFF_V1 + rowi[i] * 64 + lane + 32];
        ns0 += ta;
        ns1 += tb;
    }
    sm[OFF_NP + wid * 64 + lane]      = ns0;
    sm[OFF_NP + wid * 64 + lane + 32] = ns1;
    __syncthreads();

    // ================= epilogue =================
    if (tid < 64) {
        float den = 1e-8f;
#pragma unroll
        for (int w = 0; w < 8; w++) den += sm[OFF_DEN + w];
        float num = 0.0f;
#pragma unroll
        for (int w = 0; w < 8; w++) num += sm[OFF_NP + w * 64 + tid];
        out[qb + tid] = num / den;
    }
}

extern "C" void kernel_launch(void* const* d_in, const int* in_sizes, int n_in,
                              void* d_out, int out_size) {
    const float* q  = (const float*)d_in[0];
    const float* k1 = (const float*)d_in[1];
    const float* k2 = (const float*)d_in[2];
    const float* v1 = (const float*)d_in[3];
    const float* v2 = (const float*)d_in[4];
    float* out = (float*)d_out;

    cudaFuncSetAttribute(tsa_kernel, cudaFuncAttributeMaxDynamicSharedMemorySize,
                         SMEM_BYTES);
    dim3 grid(Bc * Sc * Hc);
    tsa_kernel<<<grid, NT, SMEM_BYTES>>>(q, k1, k2, v1, v2, out);
}

// round 11
// speedup vs baseline: 1.4145x; 1.4145x over previous
#include <cuda_runtime.h>
#include <cuda_bf16.h>
#include <cstdint>

// Two-simplicial attention via mma.sync.m16n8k16 bf16 split-fp32.
// One position per CTA, 256 threads (8 warps), 2 CTAs/SM.
// R11 = R10 with corrected lo-tile deltas (A: 11520, B: 9216).

constexpr int Sc = 2048, Hc = 4, Dc = 64;
constexpr float SCALE_F = 0.125f;
constexpr int NT = 256;

// ---- smem byte offsets ----
// bf16 tiles use row stride 72 elems = 144 B (16B-aligned, conflict-free ldmatrix)
constexpr int OFF_A3H   = 0;        // [80][72] bf16  k1q hi (reused as W hi)
constexpr int OFF_A3L   = 11520;    // [80][72] bf16  k1q lo (reused as W lo)
constexpr int OFF_B3H   = 23040;    // [64][72] bf16  k2 hi   rows=c, cols=d
constexpr int OFF_B3L   = 32256;
constexpr int OFF_B4H   = 41472;    // [64][72] bf16  v2^T hi rows=d, cols=c
constexpr int OFF_B4L   = 50688;
constexpr int OFF_V1F   = 59904;    // f32 [65][68]
constexpr int OFF_K1F   = 77584;    // f32 [65][64]
constexpr int OFF_K2R64 = 94224;    // f32 [64]
constexpr int OFF_V2R64 = 94480;    // f32 [64]
constexpr int OFF_WC64  = 94736;    // f32 [65]
constexpr int OFF_DEN   = 95008;    // f32 [8]
constexpr int OFF_OST   = 95056;    // f32 [8][68]
constexpr int SMEM_BYTES = 97232;   // x2 CTAs = 194.5 KB < 228 KB

constexpr int LD_A = OFF_A3L - OFF_A3H;   // 11520 ([80][72] bf16)
constexpr int LD_B = OFF_B3L - OFF_B3H;   // 9216  ([64][72] bf16) == B4L-B4H

__device__ __forceinline__ uint32_t smem_u32(const void* p) {
    uint32_t a;
    asm("{ .reg .u64 t; cvta.to.shared.u64 t, %1; cvt.u32.u64 %0, t; }" : "=r"(a) : "l"(p));
    return a;
}
__device__ __forceinline__ uint32_t bf2(float lo, float hi) {
    uint32_t r;
    asm("cvt.rn.bf16x2.f32 %0, %1, %2;" : "=r"(r) : "f"(hi), "f"(lo));
    return r;   // low half = lo, high half = hi
}
__device__ __forceinline__ void split2(float x0, float x1, uint32_t& h, uint32_t& l) {
    h = bf2(x0, x1);
    float h0 = __uint_as_float(h << 16);
    float h1 = __uint_as_float(h & 0xFFFF0000u);
    l = bf2(x0 - h0, x1 - h1);
}
__device__ __forceinline__ void ldsm4(uint32_t& r0, uint32_t& r1, uint32_t& r2,
                                      uint32_t& r3, uint32_t a) {
    asm volatile("ldmatrix.sync.aligned.m8n8.x4.shared.b16 {%0,%1,%2,%3}, [%4];"
                 : "=r"(r0), "=r"(r1), "=r"(r2), "=r"(r3) : "r"(a));
}
__device__ __forceinline__ void ldsm2(uint32_t& r0, uint32_t& r1, uint32_t a) {
    asm volatile("ldmatrix.sync.aligned.m8n8.x2.shared.b16 {%0,%1}, [%2];"
                 : "=r"(r0), "=r"(r1) : "r"(a));
}
__device__ __forceinline__ void mma16816(float* d, const uint32_t* a, const uint32_t* b) {
    asm volatile(
        "mma.sync.aligned.m16n8k16.row.col.f32.bf16.bf16.f32 "
        "{%0,%1,%2,%3}, {%4,%5,%6,%7}, {%8,%9}, {%0,%1,%2,%3};"
        : "+f"(d[0]), "+f"(d[1]), "+f"(d[2]), "+f"(d[3])
        : "r"(a[0]), "r"(a[1]), "r"(a[2]), "r"(a[3]), "r"(b[0]), "r"(b[1]));
}

__global__ void __launch_bounds__(NT, 2)
tsa_kernel(const float* __restrict__ q,
           const float* __restrict__ k1,
           const float* __restrict__ k2,
           const float* __restrict__ v1,
           const float* __restrict__ v2,
           float* __restrict__ out) {
    extern __shared__ __align__(1024) char smem[];
    const int tid = threadIdx.x;
    const int wid = tid >> 5, lane = tid & 31;
    const int bid = blockIdx.x;
    const int h = bid & 3;
    const int s = (bid >> 2) & 2047;
    const int b = bid >> 13;
    const int amin = 64 - s;
    const uint32_t smb = smem_u32(smem);

    // ================= prologue: loads + bf16 splits =================
    const int qb = ((b * Sc + s) * Hc + h) * Dc;
    const int dq = tid & 15;
    const float4 qv = *(const float4*)&q[qb + dq * 4];

    // zero A3 rows 65..79 (read by phase-3/4 t=4 ldmatrix; outputs masked, but
    // keep the tiles finite)
    for (int i = tid; i < 15 * 36; i += NT) {
        int r = 65 + i / 36, c = (i % 36);
        *(uint32_t*)(smem + OFF_A3H + r * 144 + c * 4) = 0u;
        *(uint32_t*)(smem + OFF_A3L + r * 144 + c * 4) = 0u;
    }

    for (int i = tid; i < 65 * 16; i += NT) {
        int r = i >> 4;
        int g = s - 64 + r; if (g < 0) g = 0;
        int off = ((b * Sc + g) * Hc + h) * Dc + dq * 4;

        // k1 fold q -> K1F f32 + A3 hi/lo bf16 (row-major [a][d], stride 72)
        float4 kv = *(const float4*)&k1[off];
        kv.x *= qv.x; kv.y *= qv.y; kv.z *= qv.z; kv.w *= qv.w;
        *(float4*)(smem + OFF_K1F + (r * 64 + dq * 4) * 4) = kv;
        {
            uint32_t h01, l01, h23, l23;
            split2(kv.x, kv.y, h01, l01);
            split2(kv.z, kv.w, h23, l23);
            *(uint2*)(smem + OFF_A3H + r * 144 + dq * 8) = make_uint2(h01, h23);
            *(uint2*)(smem + OFF_A3L + r * 144 + dq * 8) = make_uint2(l01, l23);
        }
        // k2 -> B3 ([c][d], stride 72) rows 0..63; row 64 f32
        float4 cv = *(const float4*)&k2[off];
        if (r < 64) {
            uint32_t h01, l01, h23, l23;
            split2(cv.x, cv.y, h01, l01);
            split2(cv.z, cv.w, h23, l23);
            *(uint2*)(smem + OFF_B3H + r * 144 + dq * 8) = make_uint2(h01, h23);
            *(uint2*)(smem + OFF_B3L + r * 144 + dq * 8) = make_uint2(l01, l23);
        } else {
            *(float4*)(smem + OFF_K2R64 + dq * 16) = cv;
        }
        // v1 -> V1F f32 (stride 68)
        *(float4*)(smem + OFF_V1F + (r * 68 + dq * 4) * 4) = *(const float4*)&v1[off];
        // v2 -> B4 transposed ([d][c], stride 72) rows c<64; row 64 f32
        float4 vv = *(const float4*)&v2[off];
        if (r < 64) {
            float xs[4] = {vv.x, vv.y, vv.z, vv.w};
#pragma unroll
            for (int j = 0; j < 4; j++) {
                __nv_bfloat16 hh = __float2bfloat16(xs[j]);
                __nv_bfloat16 ll = __float2bfloat16(xs[j] - __bfloat162float(hh));
                int d = dq * 4 + j;
                *(__nv_bfloat16*)(smem + OFF_B4H + d * 144 + r * 2) = hh;
                *(__nv_bfloat16*)(smem + OFF_B4L + d * 144 + r * 2) = ll;
            }
        } else {
            *(float4*)(smem + OFF_V2R64 + dq * 16) = vv;
        }
    }
    __syncthreads();

    // fragment addresses (shared by both phases)
    const int arow = (lane & 7) + 8 * ((lane >> 3) & 1);
    const int acol = 8 * (lane >> 4);
    const uint32_t aoffs = arow * 144 + acol * 2;   // + 16t*144 + K0*2
    const int brow = 8 * wid + (lane & 7);
    const int bk = 8 * ((lane >> 3) & 1);
    const uint32_t boffs3 = smb + OFF_B3H + brow * 144 + bk * 2;
    const uint32_t boffs4 = smb + OFF_B4H + brow * 144 + bk * 2;

    // ================= phase 3: scores via MMA =================
    float acc[5][4];
#pragma unroll
    for (int t = 0; t < 5; t++)
#pragma unroll
        for (int j = 0; j < 4; j++) acc[t][j] = 0.0f;

#pragma unroll
    for (int k = 0; k < 4; k++) {
        uint32_t bh[2], bl[2];
        ldsm2(bh[0], bh[1], boffs3 + k * 32);
        ldsm2(bl[0], bl[1], boffs3 + LD_B + k * 32);
#pragma unroll
        for (int t = 0; t < 5; t++) {
            uint32_t ah[4], al[4];
            uint32_t aa = smb + OFF_A3H + aoffs + t * 16 * 144 + k * 32;
            ldsm4(ah[0], ah[1], ah[2], ah[3], aa);
            ldsm4(al[0], al[1], al[2], al[3], aa + LD_A);
            mma16816(acc[t], ah, bh);
            mma16816(acc[t], ah, bl);
            mma16816(acc[t], al, bh);
        }
    }

    // ---- c = 64 score column (f32 SIMT) ----
    float dloc = 0.0f;
    if (tid < 65) {
        const float* K1Ff = (const float*)(smem + OFF_K1F) + tid * 64;
        const float* k2r = (const float*)(smem + OFF_K2R64);
        float a0 = 0.f, a1 = 0.f, a2 = 0.f, a3 = 0.f;
#pragma unroll
        for (int j = 0; j < 64; j += 4) {
            int d0 = (j + lane) & 63, d1 = (j + 1 + lane) & 63;
            int d2 = (j + 2 + lane) & 63, d3 = (j + 3 + lane) & 63;
            a0 = fmaf(K1Ff[d0], k2r[d0], a0);
            a1 = fmaf(K1Ff[d1], k2r[d1], a1);
            a2 = fmaf(K1Ff[d2], k2r[d2], a2);
            a3 = fmaf(K1Ff[d3], k2r[d3], a3);
        }
        float sc = ((a0 + a1) + (a2 + a3)) * SCALE_F;
        float w = (tid >= amin) ? __expf(sc) : 0.0f;
        ((float*)(smem + OFF_WC64))[tid] = w;
        dloc += w;
    }
    __syncthreads();   // all warps done reading A3 (k1q) before W overwrites it

    // ================= epilogue A: mask+exp, W -> A-tile =================
    {
        const int c0 = 8 * wid + 2 * (lane & 3);
        const int rb = lane >> 2;
        const bool cv0 = (c0 >= amin), cv1 = (c0 + 1 >= amin);
#pragma unroll
        for (int t = 0; t < 5; t++) {
            int r0 = 16 * t + rb, r1 = r0 + 8;
            bool av0 = (r0 <= 64) && (r0 >= amin);
            bool av1 = (r1 <= 64) && (r1 >= amin);
            float w0 = (av0 && cv0) ? __expf(acc[t][0] * SCALE_F) : 0.0f;
            float w1 = (av0 && cv1) ? __expf(acc[t][1] * SCALE_F) : 0.0f;
            float w2 = (av1 && cv0) ? __expf(acc[t][2] * SCALE_F) : 0.0f;
            float w3 = (av1 && cv1) ? __expf(acc[t][3] * SCALE_F) : 0.0f;
            dloc += (w0 + w1) + (w2 + w3);
            if (r0 <= 64) {
                uint32_t hh, ll;
                split2(w0, w1, hh, ll);
                *(uint32_t*)(smem + OFF_A3H + r0 * 144 + c0 * 2) = hh;
                *(uint32_t*)(smem + OFF_A3L + r0 * 144 + c0 * 2) = ll;
            }
            if (r1 <= 64) {
                uint32_t hh, ll;
                split2(w2, w3, hh, ll);
                *(uint32_t*)(smem + OFF_A3H + r1 * 144 + c0 * 2) = hh;
                *(uint32_t*)(smem + OFF_A3L + r1 * 144 + c0 * 2) = ll;
            }
        }
    }
#pragma unroll
    for (int o = 16; o; o >>= 1) dloc += __shfl_xor_sync(0xFFFFFFFFu, dloc, o);
    if (lane == 0) ((float*)(smem + OFF_DEN))[wid] = dloc;
    __syncthreads();   // W tile + WC64 + DEN visible

    // ================= phase 4: O = W @ V2 via MMA =================
    float acc2[5][4];
#pragma unroll
    for (int t = 0; t < 5; t++)
#pragma unroll
        for (int j = 0; j < 4; j++) acc2[t][j] = 0.0f;

#pragma unroll
    for (int k = 0; k < 4; k++) {
        uint32_t bh[2], bl[2];
        ldsm2(bh[0], bh[1], boffs4 + k * 32);
        ldsm2(bl[0], bl[1], boffs4 + LD_B + k * 32);
#pragma unroll
        for (int t = 0; t < 5; t++) {
            uint32_t ah[4], al[4];
            uint32_t aa = smb + OFF_A3H + aoffs + t * 16 * 144 + k * 32;
            ldsm4(ah[0], ah[1], ah[2], ah[3], aa);
            ldsm4(al[0], al[1], al[2], al[3], aa + LD_A);
            mma16816(acc2[t], ah, bh);
            mma16816(acc2[t], ah, bl);
            mma16816(acc2[t], al, bh);
        }
    }

    // ================= epilogue B: +c64 term, v1 fold, a-reduce =================
    {
        const int d0 = 8 * wid + 2 * (lane & 3);
        const int res = lane >> 2;
        const float* WC = (const float*)(smem + OFF_WC64);
        const float* V2R = (const float*)(smem + OFF_V2R64);
        const float* V1F = (const float*)(smem + OFF_V1F);
        float vr0 = V2R[d0], vr1 = V2R[d0 + 1];
        float s0 = 0.0f, s1 = 0.0f;
#pragma unroll
        for (int t = 0; t < 5; t++) {
#pragma unroll
            for (int hf = 0; hf < 2; hf++) {
                int a = 16 * t + res + 8 * hf;
                if (a <= 64) {
                    float wc = WC[a];
                    float o0 = acc2[t][2 * hf + 0] + wc * vr0;
                    float o1 = acc2[t][2 * hf + 1] + wc * vr1;
                    s0 += o0 * V1F[a * 68 + d0];
                    s1 += o1 * V1F[a * 68 + d0 + 1];
                }
            }
        }
        ((float*)(smem + OFF_OST))[res * 68 + d0] = s0;
        ((float*)(smem + OFF_OST))[res * 68 + d0 + 1] = s1;
    }
    __syncthreads();

    if (tid < 64) {
        const float* DEN = (const float*)(smem + OFF_DEN);
        const float* OST = (const float*)(smem + OFF_OST);
        float den = 1e-8f;
#pragma unroll
        for (int w = 0; w < 8; w++) den += DEN[w];
        float num = 0.0f;
#pragma unroll
        for (int r = 0; r < 8; r++) num += OST[r * 68 + tid];
        out[qb + tid] = num / den;
    }
}

extern "C" void kernel_launch(void* const* d_in, const int* in_sizes, int n_in,
                              void* d_out, int out_size) {
    const float* q  = (const float*)d_in[0];
    const float* k1 = (const float*)d_in[1];
    const float* k2 = (const float*)d_in[2];
    const float* v1 = (const float*)d_in[3];
    const float* v2 = (const float*)d_in[4];
    float* out = (float*)d_out;

    cudaFuncSetAttribute(tsa_kernel, cudaFuncAttributeMaxDynamicSharedMemorySize,
                         SMEM_BYTES);
    dim3 grid(2 * Sc * Hc);
    tsa_kernel<<<grid, NT, SMEM_BYTES>>>(q, k1, k2, v1, v2, out);
}

// round 12
// speedup vs baseline: 1.4752x; 1.0429x over previous
#include <cuda_runtime.h>
#include <cuda_bf16.h>
#include <cstdint>

// Two-simplicial attention via mma.sync.m16n8k16 bf16 split-fp32.
// One position per CTA, 256 threads (8 warps), 2 CTAs/SM.
// R12 = R11 + 2D warp tiling (2m x 4n), A padded to 96 rows (6 m-tiles).

constexpr int Sc = 2048, Hc = 4, Dc = 64;
constexpr float SCALE_F = 0.125f;
constexpr int NT = 256;

// ---- smem byte offsets (bf16 tiles: row stride 72 elems = 144 B) ----
constexpr int OFF_A3H   = 0;         // [96][72] bf16  k1q hi (reused as W hi)
constexpr int OFF_A3L   = 13824;     // [96][72] bf16  k1q lo (reused as W lo)
constexpr int OFF_B3H   = 27648;     // [64][72] bf16  k2 hi   rows=c, cols=d
constexpr int OFF_B3L   = 36864;
constexpr int OFF_B4H   = 46080;     // [64][72] bf16  v2^T hi rows=d, cols=c
constexpr int OFF_B4L   = 55296;
constexpr int OFF_V1F   = 64512;     // f32 [65][68]
constexpr int OFF_K1F   = 82192;     // f32 [65][64]
constexpr int OFF_K2R64 = 98832;     // f32 [64]
constexpr int OFF_V2R64 = 99088;     // f32 [64]
constexpr int OFF_WC64  = 99344;     // f32 [65]
constexpr int OFF_DEN   = 99616;     // f32 [8]
constexpr int OFF_OST   = 99648;     // f32 [16][68]
constexpr int SMEM_BYTES = 104000;   // x2 CTAs = 208 KB < 228 KB

constexpr int LD_A = OFF_A3L - OFF_A3H;   // 13824
constexpr int LD_B = OFF_B3L - OFF_B3H;   // 9216

__device__ __forceinline__ uint32_t smem_u32(const void* p) {
    uint32_t a;
    asm("{ .reg .u64 t; cvta.to.shared.u64 t, %1; cvt.u32.u64 %0, t; }" : "=r"(a) : "l"(p));
    return a;
}
__device__ __forceinline__ uint32_t bf2(float lo, float hi) {
    uint32_t r;
    asm("cvt.rn.bf16x2.f32 %0, %1, %2;" : "=r"(r) : "f"(hi), "f"(lo));
    return r;
}
__device__ __forceinline__ void split2(float x0, float x1, uint32_t& h, uint32_t& l) {
    h = bf2(x0, x1);
    float h0 = __uint_as_float(h << 16);
    float h1 = __uint_as_float(h & 0xFFFF0000u);
    l = bf2(x0 - h0, x1 - h1);
}
__device__ __forceinline__ void ldsm4(uint32_t& r0, uint32_t& r1, uint32_t& r2,
                                      uint32_t& r3, uint32_t a) {
    asm volatile("ldmatrix.sync.aligned.m8n8.x4.shared.b16 {%0,%1,%2,%3}, [%4];"
                 : "=r"(r0), "=r"(r1), "=r"(r2), "=r"(r3) : "r"(a));
}
__device__ __forceinline__ void ldsm2(uint32_t& r0, uint32_t& r1, uint32_t a) {
    asm volatile("ldmatrix.sync.aligned.m8n8.x2.shared.b16 {%0,%1}, [%2];"
                 : "=r"(r0), "=r"(r1) : "r"(a));
}
__device__ __forceinline__ void mma16816(float* d, const uint32_t* a, const uint32_t* b) {
    asm volatile(
        "mma.sync.aligned.m16n8k16.row.col.f32.bf16.bf16.f32 "
        "{%0,%1,%2,%3}, {%4,%5,%6,%7}, {%8,%9}, {%0,%1,%2,%3};"
        : "+f"(d[0]), "+f"(d[1]), "+f"(d[2]), "+f"(d[3])
        : "r"(a[0]), "r"(a[1]), "r"(a[2]), "r"(a[3]), "r"(b[0]), "r"(b[1]));
}

__global__ void __launch_bounds__(NT, 2)
tsa_kernel(const float* __restrict__ q,
           const float* __restrict__ k1,
           const float* __restrict__ k2,
           const float* __restrict__ v1,
           const float* __restrict__ v2,
           float* __restrict__ out) {
    extern __shared__ __align__(1024) char smem[];
    const int tid = threadIdx.x;
    const int wid = tid >> 5, lane = tid & 31;
    const int wm = wid & 1;        // m-group: 3 m-tiles each
    const int wn = wid >> 1;       // n-group: 2 n-tiles each
    const int bid = blockIdx.x;
    const int h = bid & 3;
    const int s = (bid >> 2) & 2047;
    const int b = bid >> 13;
    const int amin = 64 - s;
    const uint32_t smb = smem_u32(smem);

    // ================= prologue =================
    const int qb = ((b * Sc + s) * Hc + h) * Dc;
    const int dq = tid & 15;
    const float4 qv = *(const float4*)&q[qb + dq * 4];

    // zero A3 rows 65..95 (hi+lo): MMA reads them; outputs masked but must be finite
    for (int i = tid; i < 31 * 36; i += NT) {
        int r = 65 + i / 36, c = (i % 36);
        *(uint32_t*)(smem + OFF_A3H + r * 144 + c * 4) = 0u;
        *(uint32_t*)(smem + OFF_A3L + r * 144 + c * 4) = 0u;
    }

    for (int i = tid; i < 65 * 16; i += NT) {
        int r = i >> 4;
        int g = s - 64 + r; if (g < 0) g = 0;
        int off = ((b * Sc + g) * Hc + h) * Dc + dq * 4;

        float4 kv = *(const float4*)&k1[off];
        kv.x *= qv.x; kv.y *= qv.y; kv.z *= qv.z; kv.w *= qv.w;
        *(float4*)(smem + OFF_K1F + (r * 64 + dq * 4) * 4) = kv;
        {
            uint32_t h01, l01, h23, l23;
            split2(kv.x, kv.y, h01, l01);
            split2(kv.z, kv.w, h23, l23);
            *(uint2*)(smem + OFF_A3H + r * 144 + dq * 8) = make_uint2(h01, h23);
            *(uint2*)(smem + OFF_A3L + r * 144 + dq * 8) = make_uint2(l01, l23);
        }
        float4 cv = *(const float4*)&k2[off];
        if (r < 64) {
            uint32_t h01, l01, h23, l23;
            split2(cv.x, cv.y, h01, l01);
            split2(cv.z, cv.w, h23, l23);
            *(uint2*)(smem + OFF_B3H + r * 144 + dq * 8) = make_uint2(h01, h23);
            *(uint2*)(smem + OFF_B3L + r * 144 + dq * 8) = make_uint2(l01, l23);
        } else {
            *(float4*)(smem + OFF_K2R64 + dq * 16) = cv;
        }
        *(float4*)(smem + OFF_V1F + (r * 68 + dq * 4) * 4) = *(const float4*)&v1[off];
        float4 vv = *(const float4*)&v2[off];
        if (r < 64) {
            float xs[4] = {vv.x, vv.y, vv.z, vv.w};
#pragma unroll
            for (int j = 0; j < 4; j++) {
                __nv_bfloat16 hh = __float2bfloat16(xs[j]);
                __nv_bfloat16 ll = __float2bfloat16(xs[j] - __bfloat162float(hh));
                int d = dq * 4 + j;
                *(__nv_bfloat16*)(smem + OFF_B4H + d * 144 + r * 2) = hh;
                *(__nv_bfloat16*)(smem + OFF_B4L + d * 144 + r * 2) = ll;
            }
        } else {
            *(float4*)(smem + OFF_V2R64 + dq * 16) = vv;
        }
    }
    __syncthreads();

    // fragment addresses
    const int arow = (lane & 7) + 8 * ((lane >> 3) & 1);
    const int acol = 8 * (lane >> 4);
    const uint32_t aoffs = arow * 144 + acol * 2;          // + T*16*144 + k*32
    const int bk = 8 * ((lane >> 3) & 1);
    const uint32_t brow0 = (wn * 2) * 8 + (lane & 7);      // n-tile jn=0
    const uint32_t boff3 = smb + OFF_B3H + brow0 * 144 + bk * 2;  // jn=1: +8*144
    const uint32_t boff4 = smb + OFF_B4H + brow0 * 144 + bk * 2;

    // ================= phase 3: scores via MMA =================
    float acc[3][2][4];
#pragma unroll
    for (int i = 0; i < 3; i++)
#pragma unroll
        for (int j = 0; j < 2; j++)
#pragma unroll
            for (int e = 0; e < 4; e++) acc[i][j][e] = 0.0f;

#pragma unroll
    for (int k = 0; k < 4; k++) {
        uint32_t bh[2][2], bl[2][2];
#pragma unroll
        for (int j = 0; j < 2; j++) {
            ldsm2(bh[j][0], bh[j][1], boff3 + j * 8 * 144 + k * 32);
            ldsm2(bl[j][0], bl[j][1], boff3 + LD_B + j * 8 * 144 + k * 32);
        }
#pragma unroll
        for (int i = 0; i < 3; i++) {
            uint32_t ah[4], al[4];
            uint32_t aa = smb + OFF_A3H + aoffs + (wm * 3 + i) * 16 * 144 + k * 32;
            ldsm4(ah[0], ah[1], ah[2], ah[3], aa);
            ldsm4(al[0], al[1], al[2], al[3], aa + LD_A);
#pragma unroll
            for (int j = 0; j < 2; j++) {
                mma16816(acc[i][j], ah, bh[j]);
                mma16816(acc[i][j], ah, bl[j]);
                mma16816(acc[i][j], al, bh[j]);
            }
        }
    }

    // ---- c = 64 score column (f32 SIMT) ----
    float dloc = 0.0f;
    if (tid < 65) {
        const float* K1Ff = (const float*)(smem + OFF_K1F) + tid * 64;
        const float* k2r = (const float*)(smem + OFF_K2R64);
        float a0 = 0.f, a1 = 0.f, a2 = 0.f, a3 = 0.f;
#pragma unroll
        for (int j = 0; j < 64; j += 4) {
            int d0 = (j + lane) & 63, d1 = (j + 1 + lane) & 63;
            int d2 = (j + 2 + lane) & 63, d3 = (j + 3 + lane) & 63;
            a0 = fmaf(K1Ff[d0], k2r[d0], a0);
            a1 = fmaf(K1Ff[d1], k2r[d1], a1);
            a2 = fmaf(K1Ff[d2], k2r[d2], a2);
            a3 = fmaf(K1Ff[d3], k2r[d3], a3);
        }
        float sc = ((a0 + a1) + (a2 + a3)) * SCALE_F;
        float w = (tid >= amin) ? __expf(sc) : 0.0f;
        ((float*)(smem + OFF_WC64))[tid] = w;
        dloc += w;
    }
    __syncthreads();   // all warps done reading A3 (k1q) before W overwrites it

    // ================= epilogue A: mask+exp, W -> A-tile =================
    {
        const int rb = lane >> 2;
#pragma unroll
        for (int i = 0; i < 3; i++) {
            int r0 = (wm * 3 + i) * 16 + rb, r1 = r0 + 8;
            bool av0 = (r0 <= 64) && (r0 >= amin);
            bool av1 = (r1 <= 64) && (r1 >= amin);
#pragma unroll
            for (int j = 0; j < 2; j++) {
                int c0 = (wn * 2 + j) * 8 + 2 * (lane & 3);
                bool cv0 = (c0 >= amin), cv1 = (c0 + 1 >= amin);
                float w0 = (av0 && cv0) ? __expf(acc[i][j][0] * SCALE_F) : 0.0f;
                float w1 = (av0 && cv1) ? __expf(acc[i][j][1] * SCALE_F) : 0.0f;
                float w2 = (av1 && cv0) ? __expf(acc[i][j][2] * SCALE_F) : 0.0f;
                float w3 = (av1 && cv1) ? __expf(acc[i][j][3] * SCALE_F) : 0.0f;
                dloc += (w0 + w1) + (w2 + w3);
                if (r0 <= 64) {
                    uint32_t hh, ll;
                    split2(w0, w1, hh, ll);
                    *(uint32_t*)(smem + OFF_A3H + r0 * 144 + c0 * 2) = hh;
                    *(uint32_t*)(smem + OFF_A3L + r0 * 144 + c0 * 2) = ll;
                }
                if (r1 <= 64) {
                    uint32_t hh, ll;
                    split2(w2, w3, hh, ll);
                    *(uint32_t*)(smem + OFF_A3H + r1 * 144 + c0 * 2) = hh;
                    *(uint32_t*)(smem + OFF_A3L + r1 * 144 + c0 * 2) = ll;
                }
            }
        }
    }
#pragma unroll
    for (int o = 16; o; o >>= 1) dloc += __shfl_xor_sync(0xFFFFFFFFu, dloc, o);
    if (lane == 0) ((float*)(smem + OFF_DEN))[wid] = dloc;
    __syncthreads();   // W tile + WC64 + DEN visible

    // ================= phase 4: O = W @ V2 via MMA =================
    float acc2[3][2][4];
#pragma unroll
    for (int i = 0; i < 3; i++)
#pragma unroll
        for (int j = 0; j < 2; j++)
#pragma unroll
            for (int e = 0; e < 4; e++) acc2[i][j][e] = 0.0f;

#pragma unroll
    for (int k = 0; k < 4; k++) {
        uint32_t bh[2][2], bl[2][2];
#pragma unroll
        for (int j = 0; j < 2; j++) {
            ldsm2(bh[j][0], bh[j][1], boff4 + j * 8 * 144 + k * 32);
            ldsm2(bl[j][0], bl[j][1], boff4 + LD_B + j * 8 * 144 + k * 32);
        }
#pragma unroll
        for (int i = 0; i < 3; i++) {
            uint32_t ah[4], al[4];
            uint32_t aa = smb + OFF_A3H + aoffs + (wm * 3 + i) * 16 * 144 + k * 32;
            ldsm4(ah[0], ah[1], ah[2], ah[3], aa);
            ldsm4(al[0], al[1], al[2], al[3], aa + LD_A);
#pragma unroll
            for (int j = 0; j < 2; j++) {
                mma16816(acc2[i][j], ah, bh[j]);
                mma16816(acc2[i][j], ah, bl[j]);
                mma16816(acc2[i][j], al, bh[j]);
            }
        }
    }

    // ================= epilogue B: +c64 term, v1 fold, a-reduce =================
    {
        const int res = lane >> 2;
        const float* WC = (const float*)(smem + OFF_WC64);
        const float* V2R = (const float*)(smem + OFF_V2R64);
        const float* V1F = (const float*)(smem + OFF_V1F);
#pragma unroll
        for (int j = 0; j < 2; j++) {
            int d0 = (wn * 2 + j) * 8 + 2 * (lane & 3);
            float vr0 = V2R[d0], vr1 = V2R[d0 + 1];
            float s0 = 0.0f, s1 = 0.0f;
#pragma unroll
            for (int i = 0; i < 3; i++) {
#pragma unroll
                for (int hf = 0; hf < 2; hf++) {
                    int a = (wm * 3 + i) * 16 + res + 8 * hf;
                    if (a <= 64) {
                        float wc = WC[a];
                        float o0 = acc2[i][j][2 * hf + 0] + wc * vr0;
                        float o1 = acc2[i][j][2 * hf + 1] + wc * vr1;
                        s0 += o0 * V1F[a * 68 + d0];
                        s1 += o1 * V1F[a * 68 + d0 + 1];
                    }
                }
            }
            ((float*)(smem + OFF_OST))[(wm * 8 + res) * 68 + d0] = s0;
            ((float*)(smem + OFF_OST))[(wm * 8 + res) * 68 + d0 + 1] = s1;
        }
    }
    __syncthreads();

    if (tid < 64) {
        const float* DEN = (const float*)(smem + OFF_DEN);
        const float* OST = (const float*)(smem + OFF_OST);
        float den = 1e-8f;
#pragma unroll
        for (int w = 0; w < 8; w++) den += DEN[w];
        float num = 0.0f;
#pragma unroll
        for (int r = 0; r < 16; r++) num += OST[r * 68 + tid];
        out[qb + tid] = num / den;
    }
}

extern "C" void kernel_launch(void* const* d_in, const int* in_sizes, int n_in,
                              void* d_out, int out_size) {
    const float* q  = (const float*)d_in[0];
    const float* k1 = (const float*)d_in[1];
    const float* k2 = (const float*)d_in[2];
    const float* v1 = (const float*)d_in[3];
    const float* v2 = (const float*)d_in[4];
    float* out = (float*)d_out;

    cudaFuncSetAttribute(tsa_kernel, cudaFuncAttributeMaxDynamicSharedMemorySize,
                         SMEM_BYTES);
    dim3 grid(2 * Sc * Hc);
    tsa_kernel<<<grid, NT, SMEM_BYTES>>>(q, k1, k2, v1, v2, out);
}

// round 13
// speedup vs baseline: 1.8237x; 1.2363x over previous
#include <cuda_runtime.h>
#include <cuda_bf16.h>
#include <cstdint>

// Two-simplicial attention via mma.sync.m16n8k16 bf16 split-fp32.
// One position per CTA, 256 threads (8 warps), 2 CTAs/SM.
// R13 = R12 + v2 stored row-major with ldmatrix.x4.trans B-loads (phase 4)
//            + phase-3 B loads fused into ldmatrix.x4.

constexpr int Sc = 2048, Hc = 4, Dc = 64;
constexpr float SCALE_F = 0.125f;
constexpr int NT = 256;

// ---- smem byte offsets (bf16 tiles: row stride 72 elems = 144 B) ----
constexpr int OFF_A3H   = 0;         // [96][72] bf16  k1q hi (reused as W hi)
constexpr int OFF_A3L   = 13824;     // [96][72] bf16  k1q lo (reused as W lo)
constexpr int OFF_B3H   = 27648;     // [64][72] bf16  k2 hi   rows=c, cols=d
constexpr int OFF_B3L   = 36864;
constexpr int OFF_B4H   = 46080;     // [64][72] bf16  v2 hi   rows=c, cols=d (row-major!)
constexpr int OFF_B4L   = 55296;
constexpr int OFF_V1F   = 64512;     // f32 [65][68]
constexpr int OFF_K1F   = 82192;     // f32 [65][64]
constexpr int OFF_K2R64 = 98832;     // f32 [64]
constexpr int OFF_V2R64 = 99088;     // f32 [64]
constexpr int OFF_WC64  = 99344;     // f32 [65]
constexpr int OFF_DEN   = 99616;     // f32 [8]
constexpr int OFF_OST   = 99648;     // f32 [16][68]
constexpr int SMEM_BYTES = 104000;   // x2 CTAs = 208 KB < 228 KB

constexpr int LD_A = OFF_A3L - OFF_A3H;   // 13824
constexpr int LD_B = OFF_B3L - OFF_B3H;   // 9216

__device__ __forceinline__ uint32_t smem_u32(const void* p) {
    uint32_t a;
    asm("{ .reg .u64 t; cvta.to.shared.u64 t, %1; cvt.u32.u64 %0, t; }" : "=r"(a) : "l"(p));
    return a;
}
__device__ __forceinline__ uint32_t bf2(float lo, float hi) {
    uint32_t r;
    asm("cvt.rn.bf16x2.f32 %0, %1, %2;" : "=r"(r) : "f"(hi), "f"(lo));
    return r;
}
__device__ __forceinline__ void split2(float x0, float x1, uint32_t& h, uint32_t& l) {
    h = bf2(x0, x1);
    float h0 = __uint_as_float(h << 16);
    float h1 = __uint_as_float(h & 0xFFFF0000u);
    l = bf2(x0 - h0, x1 - h1);
}
__device__ __forceinline__ void ldsm4(uint32_t& r0, uint32_t& r1, uint32_t& r2,
                                      uint32_t& r3, uint32_t a) {
    asm volatile("ldmatrix.sync.aligned.m8n8.x4.shared.b16 {%0,%1,%2,%3}, [%4];"
                 : "=r"(r0), "=r"(r1), "=r"(r2), "=r"(r3) : "r"(a));
}
__device__ __forceinline__ void ldsm4t(uint32_t& r0, uint32_t& r1, uint32_t& r2,
                                       uint32_t& r3, uint32_t a) {
    asm volatile("ldmatrix.sync.aligned.m8n8.x4.trans.shared.b16 {%0,%1,%2,%3}, [%4];"
                 : "=r"(r0), "=r"(r1), "=r"(r2), "=r"(r3) : "r"(a));
}
__device__ __forceinline__ void mma16816(float* d, const uint32_t* a, const uint32_t* b) {
    asm volatile(
        "mma.sync.aligned.m16n8k16.row.col.f32.bf16.bf16.f32 "
        "{%0,%1,%2,%3}, {%4,%5,%6,%7}, {%8,%9}, {%0,%1,%2,%3};"
        : "+f"(d[0]), "+f"(d[1]), "+f"(d[2]), "+f"(d[3])
        : "r"(a[0]), "r"(a[1]), "r"(a[2]), "r"(a[3]), "r"(b[0]), "r"(b[1]));
}

__global__ void __launch_bounds__(NT, 2)
tsa_kernel(const float* __restrict__ q,
           const float* __restrict__ k1,
           const float* __restrict__ k2,
           const float* __restrict__ v1,
           const float* __restrict__ v2,
           float* __restrict__ out) {
    extern __shared__ __align__(1024) char smem[];
    const int tid = threadIdx.x;
    const int wid = tid >> 5, lane = tid & 31;
    const int wm = wid & 1;        // m-group: 3 m-tiles each
    const int wn = wid >> 1;       // n-group: 2 n-tiles each
    const int bid = blockIdx.x;
    const int h = bid & 3;
    const int s = (bid >> 2) & 2047;
    const int b = bid >> 13;
    const int amin = 64 - s;
    const uint32_t smb = smem_u32(smem);

    // ================= prologue =================
    const int qb = ((b * Sc + s) * Hc + h) * Dc;
    const int dq = tid & 15;
    const float4 qv = *(const float4*)&q[qb + dq * 4];

    // zero A3 rows 65..95 (hi+lo): MMA reads them; outputs masked but must be finite
    for (int i = tid; i < 31 * 36; i += NT) {
        int r = 65 + i / 36, c = (i % 36);
        *(uint32_t*)(smem + OFF_A3H + r * 144 + c * 4) = 0u;
        *(uint32_t*)(smem + OFF_A3L + r * 144 + c * 4) = 0u;
    }

    for (int i = tid; i < 65 * 16; i += NT) {
        int r = i >> 4;
        int g = s - 64 + r; if (g < 0) g = 0;
        int off = ((b * Sc + g) * Hc + h) * Dc + dq * 4;

        float4 kv = *(const float4*)&k1[off];
        kv.x *= qv.x; kv.y *= qv.y; kv.z *= qv.z; kv.w *= qv.w;
        *(float4*)(smem + OFF_K1F + (r * 64 + dq * 4) * 4) = kv;
        {
            uint32_t h01, l01, h23, l23;
            split2(kv.x, kv.y, h01, l01);
            split2(kv.z, kv.w, h23, l23);
            *(uint2*)(smem + OFF_A3H + r * 144 + dq * 8) = make_uint2(h01, h23);
            *(uint2*)(smem + OFF_A3L + r * 144 + dq * 8) = make_uint2(l01, l23);
        }
        float4 cv = *(const float4*)&k2[off];
        if (r < 64) {
            uint32_t h01, l01, h23, l23;
            split2(cv.x, cv.y, h01, l01);
            split2(cv.z, cv.w, h23, l23);
            *(uint2*)(smem + OFF_B3H + r * 144 + dq * 8) = make_uint2(h01, h23);
            *(uint2*)(smem + OFF_B3L + r * 144 + dq * 8) = make_uint2(l01, l23);
        } else {
            *(float4*)(smem + OFF_K2R64 + dq * 16) = cv;
        }
        *(float4*)(smem + OFF_V1F + (r * 68 + dq * 4) * 4) = *(const float4*)&v1[off];
        float4 vv = *(const float4*)&v2[off];
        if (r < 64) {
            uint32_t h01, l01, h23, l23;
            split2(vv.x, vv.y, h01, l01);
            split2(vv.z, vv.w, h23, l23);
            *(uint2*)(smem + OFF_B4H + r * 144 + dq * 8) = make_uint2(h01, h23);
            *(uint2*)(smem + OFF_B4L + r * 144 + dq * 8) = make_uint2(l01, l23);
        } else {
            *(float4*)(smem + OFF_V2R64 + dq * 16) = vv;
        }
    }
    __syncthreads();

    // fragment addresses
    const int arow = (lane & 7) + 8 * ((lane >> 3) & 1);
    const int acol = 8 * (lane >> 4);
    const uint32_t aoffs = arow * 144 + acol * 2;          // + T*16*144 + k*32
    // phase-3 B: ldsm4 non-trans. matrix m=lane>>3: j=m>>1, kh=m&1
    //   addr = B3H + ((wn*2+j)*8 + (lane&7))*144 + (k*16 + kh*8)*2
    const uint32_t b3base = smb + OFF_B3H
        + ((wn * 2 + (lane >> 4)) * 8 + (lane & 7)) * 144
        + ((lane >> 3) & 1) * 16;                          // + k*32
    // phase-4 B: ldsm4 TRANS on row-major v2 [c][d].
    //   matrix m=lane>>3: j=m>>1, kh=m&1
    //   addr = B4H + (k*16 + kh*8 + (lane&7))*144 + (wn*2+j)*16
    const uint32_t b4base = smb + OFF_B4H
        + (((lane >> 3) & 1) * 8 + (lane & 7)) * 144
        + (wn * 2 + (lane >> 4)) * 16;                     // + k*2304

    // ================= phase 3: scores via MMA =================
    float acc[3][2][4];
#pragma unroll
    for (int i = 0; i < 3; i++)
#pragma unroll
        for (int j = 0; j < 2; j++)
#pragma unroll
            for (int e = 0; e < 4; e++) acc[i][j][e] = 0.0f;

#pragma unroll
    for (int k = 0; k < 4; k++) {
        uint32_t bh[2][2], bl[2][2];
        ldsm4(bh[0][0], bh[0][1], bh[1][0], bh[1][1], b3base + k * 32);
        ldsm4(bl[0][0], bl[0][1], bl[1][0], bl[1][1], b3base + LD_B + k * 32);
#pragma unroll
        for (int i = 0; i < 3; i++) {
            uint32_t ah[4], al[4];
            uint32_t aa = smb + OFF_A3H + aoffs + (wm * 3 + i) * 16 * 144 + k * 32;
            ldsm4(ah[0], ah[1], ah[2], ah[3], aa);
            ldsm4(al[0], al[1], al[2], al[3], aa + LD_A);
#pragma unroll
            for (int j = 0; j < 2; j++) {
                mma16816(acc[i][j], ah, bh[j]);
                mma16816(acc[i][j], ah, bl[j]);
                mma16816(acc[i][j], al, bh[j]);
            }
        }
    }

    // ---- c = 64 score column (f32 SIMT) ----
    float dloc = 0.0f;
    if (tid < 65) {
        const float* K1Ff = (const float*)(smem + OFF_K1F) + tid * 64;
        const float* k2r = (const float*)(smem + OFF_K2R64);
        float a0 = 0.f, a1 = 0.f, a2 = 0.f, a3 = 0.f;
#pragma unroll
        for (int j = 0; j < 64; j += 4) {
            int d0 = (j + lane) & 63, d1 = (j + 1 + lane) & 63;
            int d2 = (j + 2 + lane) & 63, d3 = (j + 3 + lane) & 63;
            a0 = fmaf(K1Ff[d0], k2r[d0], a0);
            a1 = fmaf(K1Ff[d1], k2r[d1], a1);
            a2 = fmaf(K1Ff[d2], k2r[d2], a2);
            a3 = fmaf(K1Ff[d3], k2r[d3], a3);
        }
        float sc = ((a0 + a1) + (a2 + a3)) * SCALE_F;
        float w = (tid >= amin) ? __expf(sc) : 0.0f;
        ((float*)(smem + OFF_WC64))[tid] = w;
        dloc += w;
    }
    __syncthreads();   // all warps done reading A3 (k1q) before W overwrites it

    // ================= epilogue A: mask+exp, W -> A-tile =================
    {
        const int rb = lane >> 2;
#pragma unroll
        for (int i = 0; i < 3; i++) {
            int r0 = (wm * 3 + i) * 16 + rb, r1 = r0 + 8;
            bool av0 = (r0 <= 64) && (r0 >= amin);
            bool av1 = (r1 <= 64) && (r1 >= amin);
#pragma unroll
            for (int j = 0; j < 2; j++) {
                int c0 = (wn * 2 + j) * 8 + 2 * (lane & 3);
                bool cv0 = (c0 >= amin), cv1 = (c0 + 1 >= amin);
                float w0 = (av0 && cv0) ? __expf(acc[i][j][0] * SCALE_F) : 0.0f;
                float w1 = (av0 && cv1) ? __expf(acc[i][j][1] * SCALE_F) : 0.0f;
                float w2 = (av1 && cv0) ? __expf(acc[i][j][2] * SCALE_F) : 0.0f;
                float w3 = (av1 && cv1) ? __expf(acc[i][j][3] * SCALE_F) : 0.0f;
                dloc += (w0 + w1) + (w2 + w3);
                if (r0 <= 64) {
                    uint32_t hh, ll;
                    split2(w0, w1, hh, ll);
                    *(uint32_t*)(smem + OFF_A3H + r0 * 144 + c0 * 2) = hh;
                    *(uint32_t*)(smem + OFF_A3L + r0 * 144 + c0 * 2) = ll;
                }
                if (r1 <= 64) {
                    uint32_t hh, ll;
                    split2(w2, w3, hh, ll);
                    *(uint32_t*)(smem + OFF_A3H + r1 * 144 + c0 * 2) = hh;
                    *(uint32_t*)(smem + OFF_A3L + r1 * 144 + c0 * 2) = ll;
                }
            }
        }
    }
#pragma unroll
    for (int o = 16; o; o >>= 1) dloc += __shfl_xor_sync(0xFFFFFFFFu, dloc, o);
    if (lane == 0) ((float*)(smem + OFF_DEN))[wid] = dloc;
    __syncthreads();   // W tile + WC64 + DEN visible

    // ================= phase 4: O = W @ V2 via MMA (trans B loads) =================
    float acc2[3][2][4];
#pragma unroll
    for (int i = 0; i < 3; i++)
#pragma unroll
        for (int j = 0; j < 2; j++)
#pragma unroll
            for (int e = 0; e < 4; e++) acc2[i][j][e] = 0.0f;

#pragma unroll
    for (int k = 0; k < 4; k++) {
        uint32_t bh[2][2], bl[2][2];
        ldsm4t(bh[0][0], bh[0][1], bh[1][0], bh[1][1], b4base + k * 2304);
        ldsm4t(bl[0][0], bl[0][1], bl[1][0], bl[1][1], b4base + LD_B + k * 2304);
#pragma unroll
        for (int i = 0; i < 3; i++) {
            uint32_t ah[4], al[4];
            uint32_t aa = smb + OFF_A3H + aoffs + (wm * 3 + i) * 16 * 144 + k * 32;
            ldsm4(ah[0], ah[1], ah[2], ah[3], aa);
            ldsm4(al[0], al[1], al[2], al[3], aa + LD_A);
#pragma unroll
            for (int j = 0; j < 2; j++) {
                mma16816(acc2[i][j], ah, bh[j]);
                mma16816(acc2[i][j], ah, bl[j]);
                mma16816(acc2[i][j], al, bh[j]);
            }
        }
    }

    // ================= epilogue B: +c64 term, v1 fold, a-reduce =================
    {
        const int res = lane >> 2;
        const float* WC = (const float*)(smem + OFF_WC64);
        const float* V2R = (const float*)(smem + OFF_V2R64);
        const float* V1F = (const float*)(smem + OFF_V1F);
#pragma unroll
        for (int j = 0; j < 2; j++) {
            int d0 = (wn * 2 + j) * 8 + 2 * (lane & 3);
            float vr0 = V2R[d0], vr1 = V2R[d0 + 1];
            float s0 = 0.0f, s1 = 0.0f;
#pragma unroll
            for (int i = 0; i < 3; i++) {
#pragma unroll
                for (int hf = 0; hf < 2; hf++) {
                    int a = (wm * 3 + i) * 16 + res + 8 * hf;
                    if (a <= 64) {
                        float wc = WC[a];
                        float o0 = acc2[i][j][2 * hf + 0] + wc * vr0;
                        float o1 = acc2[i][j][2 * hf + 1] + wc * vr1;
                        s0 += o0 * V1F[a * 68 + d0];
                        s1 += o1 * V1F[a * 68 + d0 + 1];
                    }
                }
            }
            ((float*)(smem + OFF_OST))[(wm * 8 + res) * 68 + d0] = s0;
            ((float*)(smem + OFF_OST))[(wm * 8 + res) * 68 + d0 + 1] = s1;
        }
    }
    __syncthreads();

    if (tid < 64) {
        const float* DEN = (const float*)(smem + OFF_DEN);
        const float* OST = (const float*)(smem + OFF_OST);
        float den = 1e-8f;
#pragma unroll
        for (int w = 0; w < 8; w++) den += DEN[w];
        float num = 0.0f;
#pragma unroll
        for (int r = 0; r < 16; r++) num += OST[r * 68 + tid];
        out[qb + tid] = num / den;
    }
}

extern "C" void kernel_launch(void* const* d_in, const int* in_sizes, int n_in,
                              void* d_out, int out_size) {
    const float* q  = (const float*)d_in[0];
    const float* k1 = (const float*)d_in[1];
    const float* k2 = (const float*)d_in[2];
    const float* v1 = (const float*)d_in[3];
    const float* v2 = (const float*)d_in[4];
    float* out = (float*)d_out;

    cudaFuncSetAttribute(tsa_kernel, cudaFuncAttributeMaxDynamicSharedMemorySize,
                         SMEM_BYTES);
    dim3 grid(2 * Sc * Hc);
    tsa_kernel<<<grid, NT, SMEM_BYTES>>>(q, k1, k2, v1, v2, out);
}

// round 14
// speedup vs baseline: 1.9113x; 1.0480x over previous
#include <cuda_runtime.h>
#include <cuda_bf16.h>
#include <cstdint>

// Two-simplicial attention via mma.sync.m16n8k16 bf16 split-fp32.
// One position per CTA, 256 threads (8 warps), 2 CTAs/SM.
// R14 = R13 - K1F copy (c64 column reconstructs from bf16 tiles)
//            - A-row 65..95 zero loop (masked anyway)
//            + SCALE folded into q at load.

constexpr int Sc = 2048, Hc = 4, Dc = 64;
constexpr float SCALE_F = 0.125f;
constexpr int NT = 256;

// ---- smem byte offsets (bf16 tiles: row stride 72 elems = 144 B) ----
constexpr int OFF_A3H   = 0;         // [96][72] bf16  k1q hi (reused as W hi)
constexpr int OFF_A3L   = 13824;     // [96][72] bf16  k1q lo (reused as W lo)
constexpr int OFF_B3H   = 27648;     // [64][72] bf16  k2 hi   rows=c, cols=d
constexpr int OFF_B3L   = 36864;
constexpr int OFF_B4H   = 46080;     // [64][72] bf16  v2 hi   rows=c, cols=d
constexpr int OFF_B4L   = 55296;
constexpr int OFF_V1F   = 64512;     // f32 [65][68]
constexpr int OFF_K2R64 = 82192;     // f32 [64]
constexpr int OFF_V2R64 = 82448;     // f32 [64]
constexpr int OFF_WC64  = 82704;     // f32 [65]
constexpr int OFF_DEN   = 82964;     // f32 [8]
constexpr int OFF_OST   = 83008;     // f32 [16][68]
constexpr int SMEM_BYTES = 87360;    // x2 CTAs = 174.7 KB < 228 KB

constexpr int LD_A = OFF_A3L - OFF_A3H;   // 13824
constexpr int LD_B = OFF_B3L - OFF_B3H;   // 9216

__device__ __forceinline__ uint32_t smem_u32(const void* p) {
    uint32_t a;
    asm("{ .reg .u64 t; cvta.to.shared.u64 t, %1; cvt.u32.u64 %0, t; }" : "=r"(a) : "l"(p));
    return a;
}
__device__ __forceinline__ uint32_t bf2(float lo, float hi) {
    uint32_t r;
    asm("cvt.rn.bf16x2.f32 %0, %1, %2;" : "=r"(r) : "f"(hi), "f"(lo));
    return r;
}
__device__ __forceinline__ void split2(float x0, float x1, uint32_t& h, uint32_t& l) {
    h = bf2(x0, x1);
    float h0 = __uint_as_float(h << 16);
    float h1 = __uint_as_float(h & 0xFFFF0000u);
    l = bf2(x0 - h0, x1 - h1);
}
__device__ __forceinline__ float rlo(uint32_t w) { return __uint_as_float(w << 16); }
__device__ __forceinline__ float rhi(uint32_t w) { return __uint_as_float(w & 0xFFFF0000u); }
__device__ __forceinline__ void ldsm4(uint32_t& r0, uint32_t& r1, uint32_t& r2,
                                      uint32_t& r3, uint32_t a) {
    asm volatile("ldmatrix.sync.aligned.m8n8.x4.shared.b16 {%0,%1,%2,%3}, [%4];"
                 : "=r"(r0), "=r"(r1), "=r"(r2), "=r"(r3) : "r"(a));
}
__device__ __forceinline__ void ldsm4t(uint32_t& r0, uint32_t& r1, uint32_t& r2,
                                       uint32_t& r3, uint32_t a) {
    asm volatile("ldmatrix.sync.aligned.m8n8.x4.trans.shared.b16 {%0,%1,%2,%3}, [%4];"
                 : "=r"(r0), "=r"(r1), "=r"(r2), "=r"(r3) : "r"(a));
}
__device__ __forceinline__ void mma16816(float* d, const uint32_t* a, const uint32_t* b) {
    asm volatile(
        "mma.sync.aligned.m16n8k16.row.col.f32.bf16.bf16.f32 "
        "{%0,%1,%2,%3}, {%4,%5,%6,%7}, {%8,%9}, {%0,%1,%2,%3};"
        : "+f"(d[0]), "+f"(d[1]), "+f"(d[2]), "+f"(d[3])
        : "r"(a[0]), "r"(a[1]), "r"(a[2]), "r"(a[3]), "r"(b[0]), "r"(b[1]));
}

__global__ void __launch_bounds__(NT, 2)
tsa_kernel(const float* __restrict__ q,
           const float* __restrict__ k1,
           const float* __restrict__ k2,
           const float* __restrict__ v1,
           const float* __restrict__ v2,
           float* __restrict__ out) {
    extern __shared__ __align__(1024) char smem[];
    const int tid = threadIdx.x;
    const int wid = tid >> 5, lane = tid & 31;
    const int wm = wid & 1;        // m-group: 3 m-tiles each
    const int wn = wid >> 1;       // n-group: 2 n-tiles each
    const int bid = blockIdx.x;
    const int h = bid & 3;
    const int s = (bid >> 2) & 2047;
    const int b = bid >> 13;
    const int amin = 64 - s;
    const uint32_t smb = smem_u32(smem);

    // ================= prologue =================
    const int qb = ((b * Sc + s) * Hc + h) * Dc;
    const int dq = tid & 15;
    float4 qv = *(const float4*)&q[qb + dq * 4];
    qv.x *= SCALE_F; qv.y *= SCALE_F; qv.z *= SCALE_F; qv.w *= SCALE_F;

    for (int i = tid; i < 65 * 16; i += NT) {
        int r = i >> 4;
        int g = s - 64 + r; if (g < 0) g = 0;
        int off = ((b * Sc + g) * Hc + h) * Dc + dq * 4;

        float4 kv = *(const float4*)&k1[off];
        kv.x *= qv.x; kv.y *= qv.y; kv.z *= qv.z; kv.w *= qv.w;
        {
            uint32_t h01, l01, h23, l23;
            split2(kv.x, kv.y, h01, l01);
            split2(kv.z, kv.w, h23, l23);
            *(uint2*)(smem + OFF_A3H + r * 144 + dq * 8) = make_uint2(h01, h23);
            *(uint2*)(smem + OFF_A3L + r * 144 + dq * 8) = make_uint2(l01, l23);
        }
        float4 cv = *(const float4*)&k2[off];
        if (r < 64) {
            uint32_t h01, l01, h23, l23;
            split2(cv.x, cv.y, h01, l01);
            split2(cv.z, cv.w, h23, l23);
            *(uint2*)(smem + OFF_B3H + r * 144 + dq * 8) = make_uint2(h01, h23);
            *(uint2*)(smem + OFF_B3L + r * 144 + dq * 8) = make_uint2(l01, l23);
        } else {
            *(float4*)(smem + OFF_K2R64 + dq * 16) = cv;
        }
        *(float4*)(smem + OFF_V1F + (r * 68 + dq * 4) * 4) = *(const float4*)&v1[off];
        float4 vv = *(const float4*)&v2[off];
        if (r < 64) {
            uint32_t h01, l01, h23, l23;
            split2(vv.x, vv.y, h01, l01);
            split2(vv.z, vv.w, h23, l23);
            *(uint2*)(smem + OFF_B4H + r * 144 + dq * 8) = make_uint2(h01, h23);
            *(uint2*)(smem + OFF_B4L + r * 144 + dq * 8) = make_uint2(l01, l23);
        } else {
            *(float4*)(smem + OFF_V2R64 + dq * 16) = vv;
        }
    }
    __syncthreads();

    // fragment addresses
    const int arow = (lane & 7) + 8 * ((lane >> 3) & 1);
    const int acol = 8 * (lane >> 4);
    const uint32_t aoffs = arow * 144 + acol * 2;          // + T*16*144 + k*32
    const uint32_t b3base = smb + OFF_B3H
        + ((wn * 2 + (lane >> 4)) * 8 + (lane & 7)) * 144
        + ((lane >> 3) & 1) * 16;                          // + k*32
    const uint32_t b4base = smb + OFF_B4H
        + (((lane >> 3) & 1) * 8 + (lane & 7)) * 144
        + (wn * 2 + (lane >> 4)) * 16;                     // + k*2304

    // ================= phase 3: scores via MMA (pre-scaled) =================
    float acc[3][2][4];
#pragma unroll
    for (int i = 0; i < 3; i++)
#pragma unroll
        for (int j = 0; j < 2; j++)
#pragma unroll
            for (int e = 0; e < 4; e++) acc[i][j][e] = 0.0f;

#pragma unroll
    for (int k = 0; k < 4; k++) {
        uint32_t bh[2][2], bl[2][2];
        ldsm4(bh[0][0], bh[0][1], bh[1][0], bh[1][1], b3base + k * 32);
        ldsm4(bl[0][0], bl[0][1], bl[1][0], bl[1][1], b3base + LD_B + k * 32);
#pragma unroll
        for (int i = 0; i < 3; i++) {
            uint32_t ah[4], al[4];
            uint32_t aa = smb + OFF_A3H + aoffs + (wm * 3 + i) * 16 * 144 + k * 32;
            ldsm4(ah[0], ah[1], ah[2], ah[3], aa);
            ldsm4(al[0], al[1], al[2], al[3], aa + LD_A);
#pragma unroll
            for (int j = 0; j < 2; j++) {
                mma16816(acc[i][j], ah, bh[j]);
                mma16816(acc[i][j], ah, bl[j]);
                mma16816(acc[i][j], al, bh[j]);
            }
        }
    }

    // ---- c = 64 score column (f32 SIMT, k1q reconstructed from bf16 tiles) ----
    float dloc = 0.0f;
    if (tid < 65) {
        const char* rowH = smem + OFF_A3H + tid * 144;
        const char* rowL = smem + OFF_A3L + tid * 144;
        const float* k2r = (const float*)(smem + OFF_K2R64);
        float a0 = 0.f, a1 = 0.f;
#pragma unroll
        for (int j = 0; j < 8; j++) {
            uint4 hh = *(const uint4*)(rowH + j * 16);
            uint4 ll = *(const uint4*)(rowL + j * 16);
            const float* kr = k2r + j * 8;
            a0 = fmaf(rlo(hh.x) + rlo(ll.x), kr[0], a0);
            a1 = fmaf(rhi(hh.x) + rhi(ll.x), kr[1], a1);
            a0 = fmaf(rlo(hh.y) + rlo(ll.y), kr[2], a0);
            a1 = fmaf(rhi(hh.y) + rhi(ll.y), kr[3], a1);
            a0 = fmaf(rlo(hh.z) + rlo(ll.z), kr[4], a0);
            a1 = fmaf(rhi(hh.z) + rhi(ll.z), kr[5], a1);
            a0 = fmaf(rlo(hh.w) + rlo(ll.w), kr[6], a0);
            a1 = fmaf(rhi(hh.w) + rhi(ll.w), kr[7], a1);
        }
        float sc = a0 + a1;   // already scaled via q
        float w = (tid >= amin) ? __expf(sc) : 0.0f;
        ((float*)(smem + OFF_WC64))[tid] = w;
        dloc += w;
    }
    __syncthreads();   // all warps done reading A3 (k1q) before W overwrites it

    // ================= epilogue A: mask+exp, W -> A-tile =================
    {
        const int rb = lane >> 2;
#pragma unroll
        for (int i = 0; i < 3; i++) {
            int r0 = (wm * 3 + i) * 16 + rb, r1 = r0 + 8;
            bool av0 = (r0 <= 64) && (r0 >= amin);
            bool av1 = (r1 <= 64) && (r1 >= amin);
#pragma unroll
            for (int j = 0; j < 2; j++) {
                int c0 = (wn * 2 + j) * 8 + 2 * (lane & 3);
                bool cv0 = (c0 >= amin), cv1 = (c0 + 1 >= amin);
                float w0 = (av0 && cv0) ? __expf(acc[i][j][0]) : 0.0f;
                float w1 = (av0 && cv1) ? __expf(acc[i][j][1]) : 0.0f;
                float w2 = (av1 && cv0) ? __expf(acc[i][j][2]) : 0.0f;
                float w3 = (av1 && cv1) ? __expf(acc[i][j][3]) : 0.0f;
                dloc += (w0 + w1) + (w2 + w3);
                if (r0 <= 64) {
                    uint32_t hh, ll;
                    split2(w0, w1, hh, ll);
                    *(uint32_t*)(smem + OFF_A3H + r0 * 144 + c0 * 2) = hh;
                    *(uint32_t*)(smem + OFF_A3L + r0 * 144 + c0 * 2) = ll;
                }
                if (r1 <= 64) {
                    uint32_t hh, ll;
                    split2(w2, w3, hh, ll);
                    *(uint32_t*)(smem + OFF_A3H + r1 * 144 + c0 * 2) = hh;
                    *(uint32_t*)(smem + OFF_A3L + r1 * 144 + c0 * 2) = ll;
                }
            }
        }
    }
#pragma unroll
    for (int o = 16; o; o >>= 1) dloc += __shfl_xor_sync(0xFFFFFFFFu, dloc, o);
    if (lane == 0) ((float*)(smem + OFF_DEN))[wid] = dloc;
    __syncthreads();   // W tile + WC64 + DEN visible

    // ================= phase 4: O = W @ V2 via MMA (trans B loads) =================
    float acc2[3][2][4];
#pragma unroll
    for (int i = 0; i < 3; i++)
#pragma unroll
        for (int j = 0; j < 2; j++)
#pragma unroll
            for (int e = 0; e < 4; e++) acc2[i][j][e] = 0.0f;

#pragma unroll
    for (int k = 0; k < 4; k++) {
        uint32_t bh[2][2], bl[2][2];
        ldsm4t(bh[0][0], bh[0][1], bh[1][0], bh[1][1], b4base + k * 2304);
        ldsm4t(bl[0][0], bl[0][1], bl[1][0], bl[1][1], b4base + LD_B + k * 2304);
#pragma unroll
        for (int i = 0; i < 3; i++) {
            uint32_t ah[4], al[4];
            uint32_t aa = smb + OFF_A3H + aoffs + (wm * 3 + i) * 16 * 144 + k * 32;
            ldsm4(ah[0], ah[1], ah[2], ah[3], aa);
            ldsm4(al[0], al[1], al[2], al[3], aa + LD_A);
#pragma unroll
            for (int j = 0; j < 2; j++) {
                mma16816(acc2[i][j], ah, bh[j]);
                mma16816(acc2[i][j], ah, bl[j]);
                mma16816(acc2[i][j], al, bh[j]);
            }
        }
    }

    // ================= epilogue B: +c64 term, v1 fold, a-reduce =================
    {
        const int res = lane >> 2;
        const float* WC = (const float*)(smem + OFF_WC64);
        const float* V2R = (const float*)(smem + OFF_V2R64);
        const float* V1F = (const float*)(smem + OFF_V1F);
#pragma unroll
        for (int j = 0; j < 2; j++) {
            int d0 = (wn * 2 + j) * 8 + 2 * (lane & 3);
            float vr0 = V2R[d0], vr1 = V2R[d0 + 1];
            float s0 = 0.0f, s1 = 0.0f;
#pragma unroll
            for (int i = 0; i < 3; i++) {
#pragma unroll
                for (int hf = 0; hf < 2; hf++) {
                    int a = (wm * 3 + i) * 16 + res + 8 * hf;
                    if (a <= 64) {
                        float wc = WC[a];
                        float o0 = acc2[i][j][2 * hf + 0] + wc * vr0;
                        float o1 = acc2[i][j][2 * hf + 1] + wc * vr1;
                        s0 += o0 * V1F[a * 68 + d0];
                        s1 += o1 * V1F[a * 68 + d0 + 1];
                    }
                }
            }
            ((float*)(smem + OFF_OST))[(wm * 8 + res) * 68 + d0] = s0;
            ((float*)(smem + OFF_OST))[(wm * 8 + res) * 68 + d0 + 1] = s1;
        }
    }
    __syncthreads();

    if (tid < 64) {
        const float* DEN = (const float*)(smem + OFF_DEN);
        const float* OST = (const float*)(smem + OFF_OST);
        float den = 1e-8f;
#pragma unroll
        for (int w = 0; w < 8; w++) den += DEN[w];
        float num = 0.0f;
#pragma unroll
        for (int r = 0; r < 16; r++) num += OST[r * 68 + tid];
        out[qb + tid] = num / den;
    }
}

extern "C" void kernel_launch(void* const* d_in, const int* in_sizes, int n_in,
                              void* d_out, int out_size) {
    const float* q  = (const float*)d_in[0];
    const float* k1 = (const float*)d_in[1];
    const float* k2 = (const float*)d_in[2];
    const float* v1 = (const float*)d_in[3];
    const float* v2 = (const float*)d_in[4];
    float* out = (float*)d_out;

    cudaFuncSetAttribute(tsa_kernel, cudaFuncAttributeMaxDynamicSharedMemorySize,
                         SMEM_BYTES);
    dim3 grid(2 * Sc * Hc);
    tsa_kernel<<<grid, NT, SMEM_BYTES>>>(q, k1, k2, v1, v2, out);
}

// round 15
// speedup vs baseline: 2.0309x; 1.0626x over previous
#include <cuda_runtime.h>
#include <cuda_bf16.h>
#include <cstdint>

// Two-simplicial attention via mma.sync.m16n8k16 bf16 split-fp32.
// One position per CTA, 256 threads (8 warps), 2 CTAs/SM.
// R15 = R14 - m-tile 5 (M 96->80; wm=1 warps own 2 m-tiles)
//            + exp2f with log2e folded into q.

constexpr int Sc = 2048, Hc = 4, Dc = 64;
constexpr float QSCALE = 0.125f * 1.4426950408889634f;  // SCALE * log2(e)
constexpr int NT = 256;

// ---- smem byte offsets (bf16 tiles: row stride 72 elems = 144 B) ----
constexpr int OFF_A3H   = 0;         // [80][72] bf16  k1q hi (reused as W hi)
constexpr int OFF_A3L   = 11520;     // [80][72] bf16  k1q lo (reused as W lo)
constexpr int OFF_B3H   = 23040;     // [64][72] bf16  k2 hi   rows=c, cols=d
constexpr int OFF_B3L   = 32256;
constexpr int OFF_B4H   = 41472;     // [64][72] bf16  v2 hi   rows=c, cols=d
constexpr int OFF_B4L   = 50688;
constexpr int OFF_V1F   = 59904;     // f32 [65][68]
constexpr int OFF_K2R64 = 77584;     // f32 [64]
constexpr int OFF_V2R64 = 77840;     // f32 [64]
constexpr int OFF_WC64  = 78096;     // f32 [65]
constexpr int OFF_DEN   = 78356;     // f32 [8]
constexpr int OFF_OST   = 78400;     // f32 [16][68]
constexpr int SMEM_BYTES = 82752;    // x2 CTAs = 165.5 KB < 228 KB

constexpr int LD_A = OFF_A3L - OFF_A3H;   // 11520
constexpr int LD_B = OFF_B3L - OFF_B3H;   // 9216

__device__ __forceinline__ uint32_t smem_u32(const void* p) {
    uint32_t a;
    asm("{ .reg .u64 t; cvta.to.shared.u64 t, %1; cvt.u32.u64 %0, t; }" : "=r"(a) : "l"(p));
    return a;
}
__device__ __forceinline__ uint32_t bf2(float lo, float hi) {
    uint32_t r;
    asm("cvt.rn.bf16x2.f32 %0, %1, %2;" : "=r"(r) : "f"(hi), "f"(lo));
    return r;
}
__device__ __forceinline__ void split2(float x0, float x1, uint32_t& h, uint32_t& l) {
    h = bf2(x0, x1);
    float h0 = __uint_as_float(h << 16);
    float h1 = __uint_as_float(h & 0xFFFF0000u);
    l = bf2(x0 - h0, x1 - h1);
}
__device__ __forceinline__ float rlo(uint32_t w) { return __uint_as_float(w << 16); }
__device__ __forceinline__ float rhi(uint32_t w) { return __uint_as_float(w & 0xFFFF0000u); }
__device__ __forceinline__ void ldsm4(uint32_t& r0, uint32_t& r1, uint32_t& r2,
                                      uint32_t& r3, uint32_t a) {
    asm volatile("ldmatrix.sync.aligned.m8n8.x4.shared.b16 {%0,%1,%2,%3}, [%4];"
                 : "=r"(r0), "=r"(r1), "=r"(r2), "=r"(r3) : "r"(a));
}
__device__ __forceinline__ void ldsm4t(uint32_t& r0, uint32_t& r1, uint32_t& r2,
                                       uint32_t& r3, uint32_t a) {
    asm volatile("ldmatrix.sync.aligned.m8n8.x4.trans.shared.b16 {%0,%1,%2,%3}, [%4];"
                 : "=r"(r0), "=r"(r1), "=r"(r2), "=r"(r3) : "r"(a));
}
__device__ __forceinline__ void mma16816(float* d, const uint32_t* a, const uint32_t* b) {
    asm volatile(
        "mma.sync.aligned.m16n8k16.row.col.f32.bf16.bf16.f32 "
        "{%0,%1,%2,%3}, {%4,%5,%6,%7}, {%8,%9}, {%0,%1,%2,%3};"
        : "+f"(d[0]), "+f"(d[1]), "+f"(d[2]), "+f"(d[3])
        : "r"(a[0]), "r"(a[1]), "r"(a[2]), "r"(a[3]), "r"(b[0]), "r"(b[1]));
}

__global__ void __launch_bounds__(NT, 2)
tsa_kernel(const float* __restrict__ q,
           const float* __restrict__ k1,
           const float* __restrict__ k2,
           const float* __restrict__ v1,
           const float* __restrict__ v2,
           float* __restrict__ out) {
    extern __shared__ __align__(1024) char smem[];
    const int tid = threadIdx.x;
    const int wid = tid >> 5, lane = tid & 31;
    const int wm = wid & 1;          // m-group: tiles {0,1,2} or {3,4}
    const int wn = wid >> 1;         // n-group: 2 n-tiles each
    const int nti = 3 - wm;          // m-tiles owned by this warp
    const int bid = blockIdx.x;
    const int h = bid & 3;
    const int s = (bid >> 2) & 2047;
    const int b = bid >> 13;
    const int amin = 64 - s;
    const uint32_t smb = smem_u32(smem);

    // ================= prologue =================
    const int qb = ((b * Sc + s) * Hc + h) * Dc;
    const int dq = tid & 15;
    float4 qv = *(const float4*)&q[qb + dq * 4];
    qv.x *= QSCALE; qv.y *= QSCALE; qv.z *= QSCALE; qv.w *= QSCALE;

    for (int i = tid; i < 65 * 16; i += NT) {
        int r = i >> 4;
        int g = s - 64 + r; if (g < 0) g = 0;
        int off = ((b * Sc + g) * Hc + h) * Dc + dq * 4;

        float4 kv = *(const float4*)&k1[off];
        kv.x *= qv.x; kv.y *= qv.y; kv.z *= qv.z; kv.w *= qv.w;
        {
            uint32_t h01, l01, h23, l23;
            split2(kv.x, kv.y, h01, l01);
            split2(kv.z, kv.w, h23, l23);
            *(uint2*)(smem + OFF_A3H + r * 144 + dq * 8) = make_uint2(h01, h23);
            *(uint2*)(smem + OFF_A3L + r * 144 + dq * 8) = make_uint2(l01, l23);
        }
        float4 cv = *(const float4*)&k2[off];
        if (r < 64) {
            uint32_t h01, l01, h23, l23;
            split2(cv.x, cv.y, h01, l01);
            split2(cv.z, cv.w, h23, l23);
            *(uint2*)(smem + OFF_B3H + r * 144 + dq * 8) = make_uint2(h01, h23);
            *(uint2*)(smem + OFF_B3L + r * 144 + dq * 8) = make_uint2(l01, l23);
        } else {
            *(float4*)(smem + OFF_K2R64 + dq * 16) = cv;
        }
        *(float4*)(smem + OFF_V1F + (r * 68 + dq * 4) * 4) = *(const float4*)&v1[off];
        float4 vv = *(const float4*)&v2[off];
        if (r < 64) {
            uint32_t h01, l01, h23, l23;
            split2(vv.x, vv.y, h01, l01);
            split2(vv.z, vv.w, h23, l23);
            *(uint2*)(smem + OFF_B4H + r * 144 + dq * 8) = make_uint2(h01, h23);
            *(uint2*)(smem + OFF_B4L + r * 144 + dq * 8) = make_uint2(l01, l23);
        } else {
            *(float4*)(smem + OFF_V2R64 + dq * 16) = vv;
        }
    }
    __syncthreads();

    // fragment addresses
    const int arow = (lane & 7) + 8 * ((lane >> 3) & 1);
    const int acol = 8 * (lane >> 4);
    const uint32_t aoffs = arow * 144 + acol * 2;          // + T*16*144 + k*32
    const uint32_t b3base = smb + OFF_B3H
        + ((wn * 2 + (lane >> 4)) * 8 + (lane & 7)) * 144
        + ((lane >> 3) & 1) * 16;                          // + k*32
    const uint32_t b4base = smb + OFF_B4H
        + (((lane >> 3) & 1) * 8 + (lane & 7)) * 144
        + (wn * 2 + (lane >> 4)) * 16;                     // + k*2304

    // ================= phase 3: scores via MMA (pre-scaled, log2 domain) =========
    float acc[3][2][4];
#pragma unroll
    for (int i = 0; i < 3; i++)
#pragma unroll
        for (int j = 0; j < 2; j++)
#pragma unroll
            for (int e = 0; e < 4; e++) acc[i][j][e] = 0.0f;

#pragma unroll
    for (int k = 0; k < 4; k++) {
        uint32_t bh[2][2], bl[2][2];
        ldsm4(bh[0][0], bh[0][1], bh[1][0], bh[1][1], b3base + k * 32);
        ldsm4(bl[0][0], bl[0][1], bl[1][0], bl[1][1], b3base + LD_B + k * 32);
#pragma unroll
        for (int i = 0; i < 3; i++) {
            if (i < nti) {
                uint32_t ah[4], al[4];
                uint32_t aa = smb + OFF_A3H + aoffs + (wm * 3 + i) * 16 * 144 + k * 32;
                ldsm4(ah[0], ah[1], ah[2], ah[3], aa);
                ldsm4(al[0], al[1], al[2], al[3], aa + LD_A);
#pragma unroll
                for (int j = 0; j < 2; j++) {
                    mma16816(acc[i][j], ah, bh[j]);
                    mma16816(acc[i][j], ah, bl[j]);
                    mma16816(acc[i][j], al, bh[j]);
                }
            }
        }
    }

    // ---- c = 64 score column (f32 SIMT, k1q reconstructed from bf16 tiles) ----
    float dloc = 0.0f;
    if (tid < 65) {
        const char* rowH = smem + OFF_A3H + tid * 144;
        const char* rowL = smem + OFF_A3L + tid * 144;
        const float* k2r = (const float*)(smem + OFF_K2R64);
        float a0 = 0.f, a1 = 0.f;
#pragma unroll
        for (int j = 0; j < 8; j++) {
            uint4 hh = *(const uint4*)(rowH + j * 16);
            uint4 ll = *(const uint4*)(rowL + j * 16);
            const float* kr = k2r + j * 8;
            a0 = fmaf(rlo(hh.x) + rlo(ll.x), kr[0], a0);
            a1 = fmaf(rhi(hh.x) + rhi(ll.x), kr[1], a1);
            a0 = fmaf(rlo(hh.y) + rlo(ll.y), kr[2], a0);
            a1 = fmaf(rhi(hh.y) + rhi(ll.y), kr[3], a1);
            a0 = fmaf(rlo(hh.z) + rlo(ll.z), kr[4], a0);
            a1 = fmaf(rhi(hh.z) + rhi(ll.z), kr[5], a1);
            a0 = fmaf(rlo(hh.w) + rlo(ll.w), kr[6], a0);
            a1 = fmaf(rhi(hh.w) + rhi(ll.w), kr[7], a1);
        }
        float w = (tid >= amin) ? exp2f(a0 + a1) : 0.0f;
        ((float*)(smem + OFF_WC64))[tid] = w;
        dloc += w;
    }
    __syncthreads();   // all warps done reading A3 (k1q) before W overwrites it

    // ================= epilogue A: mask+exp, W -> A-tile =================
    {
        const int rb = lane >> 2;
#pragma unroll
        for (int i = 0; i < 3; i++) {
            if (i < nti) {
                int r0 = (wm * 3 + i) * 16 + rb, r1 = r0 + 8;
                bool av0 = (r0 <= 64) && (r0 >= amin);
                bool av1 = (r1 <= 64) && (r1 >= amin);
#pragma unroll
                for (int j = 0; j < 2; j++) {
                    int c0 = (wn * 2 + j) * 8 + 2 * (lane & 3);
                    bool cv0 = (c0 >= amin), cv1 = (c0 + 1 >= amin);
                    float w0 = (av0 && cv0) ? exp2f(acc[i][j][0]) : 0.0f;
                    float w1 = (av0 && cv1) ? exp2f(acc[i][j][1]) : 0.0f;
                    float w2 = (av1 && cv0) ? exp2f(acc[i][j][2]) : 0.0f;
                    float w3 = (av1 && cv1) ? exp2f(acc[i][j][3]) : 0.0f;
                    dloc += (w0 + w1) + (w2 + w3);
                    if (r0 <= 64) {
                        uint32_t hh, ll;
                        split2(w0, w1, hh, ll);
                        *(uint32_t*)(smem + OFF_A3H + r0 * 144 + c0 * 2) = hh;
                        *(uint32_t*)(smem + OFF_A3L + r0 * 144 + c0 * 2) = ll;
                    }
                    if (r1 <= 64) {
                        uint32_t hh, ll;
                        split2(w2, w3, hh, ll);
                        *(uint32_t*)(smem + OFF_A3H + r1 * 144 + c0 * 2) = hh;
                        *(uint32_t*)(smem + OFF_A3L + r1 * 144 + c0 * 2) = ll;
                    }
                }
            }
        }
    }
#pragma unroll
    for (int o = 16; o; o >>= 1) dloc += __shfl_xor_sync(0xFFFFFFFFu, dloc, o);
    if (lane == 0) ((float*)(smem + OFF_DEN))[wid] = dloc;
    __syncthreads();   // W tile + WC64 + DEN visible

    // ================= phase 4: O = W @ V2 via MMA (trans B loads) =================
    float acc2[3][2][4];
#pragma unroll
    for (int i = 0; i < 3; i++)
#pragma unroll
        for (int j = 0; j < 2; j++)
#pragma unroll
            for (int e = 0; e < 4; e++) acc2[i][j][e] = 0.0f;

#pragma unroll
    for (int k = 0; k < 4; k++) {
        uint32_t bh[2][2], bl[2][2];
        ldsm4t(bh[0][0], bh[0][1], bh[1][0], bh[1][1], b4base + k * 2304);
        ldsm4t(bl[0][0], bl[0][1], bl[1][0], bl[1][1], b4base + LD_B + k * 2304);
#pragma unroll
        for (int i = 0; i < 3; i++) {
            if (i < nti) {
                uint32_t ah[4], al[4];
                uint32_t aa = smb + OFF_A3H + aoffs + (wm * 3 + i) * 16 * 144 + k * 32;
                ldsm4(ah[0], ah[1], ah[2], ah[3], aa);
                ldsm4(al[0], al[1], al[2], al[3], aa + LD_A);
#pragma unroll
                for (int j = 0; j < 2; j++) {
                    mma16816(acc2[i][j], ah, bh[j]);
                    mma16816(acc2[i][j], ah, bl[j]);
                    mma16816(acc2[i][j], al, bh[j]);
                }
            }
        }
    }

    // ================= epilogue B: +c64 term, v1 fold, a-reduce =================
    {
        const int res = lane >> 2;
        const float* WC = (const float*)(smem + OFF_WC64);
        const float* V2R = (const float*)(smem + OFF_V2R64);
        const float* V1F = (const float*)(smem + OFF_V1F);
#pragma unroll
        for (int j = 0; j < 2; j++) {
            int d0 = (wn * 2 + j) * 8 + 2 * (lane & 3);
            float vr0 = V2R[d0], vr1 = V2R[d0 + 1];
            float s0 = 0.0f, s1 = 0.0f;
#pragma unroll
            for (int i = 0; i < 3; i++) {
                if (i < nti) {
#pragma unroll
                    for (int hf = 0; hf < 2; hf++) {
                        int a = (wm * 3 + i) * 16 + res + 8 * hf;
                        if (a <= 64) {
                            float wc = WC[a];
                            float o0 = acc2[i][j][2 * hf + 0] + wc * vr0;
                            float o1 = acc2[i][j][2 * hf + 1] + wc * vr1;
                            s0 += o0 * V1F[a * 68 + d0];
                            s1 += o1 * V1F[a * 68 + d0 + 1];
                        }
                    }
                }
            }
            ((float*)(smem + OFF_OST))[(wm * 8 + res) * 68 + d0] = s0;
            ((float*)(smem + OFF_OST))[(wm * 8 + res) * 68 + d0 + 1] = s1;
        }
    }
    __syncthreads();

    if (tid < 64) {
        const float* DEN = (const float*)(smem + OFF_DEN);
        const float* OST = (const float*)(smem + OFF_OST);
        float den = 1e-8f;
#pragma unroll
        for (int w = 0; w < 8; w++) den += DEN[w];
        float num = 0.0f;
#pragma unroll
        for (int r = 0; r < 16; r++) num += OST[r * 68 + tid];
        out[qb + tid] = num / den;
    }
}

extern "C" void kernel_launch(void* const* d_in, const int* in_sizes, int n_in,
                              void* d_out, int out_size) {
    const float* q  = (const float*)d_in[0];
    const float* k1 = (const float*)d_in[1];
    const float* k2 = (const float*)d_in[2];
    const float* v1 = (const float*)d_in[3];
    const float* v2 = (const float*)d_in[4];
    float* out = (float*)d_out;

    cudaFuncSetAttribute(tsa_kernel, cudaFuncAttributeMaxDynamicSharedMemorySize,
                         SMEM_BYTES);
    dim3 grid(2 * Sc * Hc);
    tsa_kernel<<<grid, NT, SMEM_BYTES>>>(q, k1, k2, v1, v2, out);
}

// round 16
// speedup vs baseline: 2.3337x; 1.1491x over previous
#include <cuda_runtime.h>
#include <cuda_bf16.h>
#include <cstdint>

// Two-simplicial attention via mma.sync.m16n8k16 bf16 split-fp32.
// One position per CTA, 256 threads (8 warps), 3 CTAs/SM.
// R16 = R15 with smem compacted (A tiles 65 real rows w/ overlap-read tail;
//       OST aliased onto dead B3H) -> 74.1 KB -> 3 CTAs/SM.

constexpr int Sc = 2048, Hc = 4, Dc = 64;
constexpr float QSCALE = 0.125f * 1.4426950408889634f;  // SCALE * log2(e)
constexpr int NT = 256;

// ---- smem byte offsets (bf16 tiles: row stride 72 elems = 144 B) ----
// A3H/A3L hold 65 real rows (9360 B); ldmatrix reads rows 65..79 spill into the
// following buffer as masked garbage (proven safe in R14/15).
constexpr int OFF_A3H   = 0;         // [65+][72] bf16  k1q hi (reused as W hi)
constexpr int OFF_A3L   = 9360;      // [65+][72] bf16  k1q lo (reused as W lo)
constexpr int OFF_B3H   = 18720;     // [64][72] bf16  k2 hi   rows=c, cols=d
constexpr int OFF_B3L   = 27936;
constexpr int OFF_B4H   = 37152;     // [64][72] bf16  v2 hi   rows=c, cols=d
constexpr int OFF_B4L   = 46368;
constexpr int OFF_V1F   = 55584;     // f32 [65][68]
constexpr int OFF_K2R64 = 73264;     // f32 [64]
constexpr int OFF_V2R64 = 73520;     // f32 [64]
constexpr int OFF_WC64  = 73776;     // f32 [65]
constexpr int OFF_DEN   = 74036;     // f32 [8]
constexpr int OFF_OST   = OFF_B3H;   // f32 [16][68] aliased onto dead B3H
constexpr int SMEM_BYTES = 74080;    // x3 CTAs = 222.2 KB <= 228 KB

constexpr int LD_A = OFF_A3L - OFF_A3H;   // 9360
constexpr int LD_B = OFF_B3L - OFF_B3H;   // 9216

__device__ __forceinline__ uint32_t smem_u32(const void* p) {
    uint32_t a;
    asm("{ .reg .u64 t; cvta.to.shared.u64 t, %1; cvt.u32.u64 %0, t; }" : "=r"(a) : "l"(p));
    return a;
}
__device__ __forceinline__ uint32_t bf2(float lo, float hi) {
    uint32_t r;
    asm("cvt.rn.bf16x2.f32 %0, %1, %2;" : "=r"(r) : "f"(hi), "f"(lo));
    return r;
}
__device__ __forceinline__ void split2(float x0, float x1, uint32_t& h, uint32_t& l) {
    h = bf2(x0, x1);
    float h0 = __uint_as_float(h << 16);
    float h1 = __uint_as_float(h & 0xFFFF0000u);
    l = bf2(x0 - h0, x1 - h1);
}
__device__ __forceinline__ float rlo(uint32_t w) { return __uint_as_float(w << 16); }
__device__ __forceinline__ float rhi(uint32_t w) { return __uint_as_float(w & 0xFFFF0000u); }
__device__ __forceinline__ void ldsm4(uint32_t& r0, uint32_t& r1, uint32_t& r2,
                                      uint32_t& r3, uint32_t a) {
    asm volatile("ldmatrix.sync.aligned.m8n8.x4.shared.b16 {%0,%1,%2,%3}, [%4];"
                 : "=r"(r0), "=r"(r1), "=r"(r2), "=r"(r3) : "r"(a));
}
__device__ __forceinline__ void ldsm4t(uint32_t& r0, uint32_t& r1, uint32_t& r2,
                                       uint32_t& r3, uint32_t a) {
    asm volatile("ldmatrix.sync.aligned.m8n8.x4.trans.shared.b16 {%0,%1,%2,%3}, [%4];"
                 : "=r"(r0), "=r"(r1), "=r"(r2), "=r"(r3) : "r"(a));
}
__device__ __forceinline__ void mma16816(float* d, const uint32_t* a, const uint32_t* b) {
    asm volatile(
        "mma.sync.aligned.m16n8k16.row.col.f32.bf16.bf16.f32 "
        "{%0,%1,%2,%3}, {%4,%5,%6,%7}, {%8,%9}, {%0,%1,%2,%3};"
        : "+f"(d[0]), "+f"(d[1]), "+f"(d[2]), "+f"(d[3])
        : "r"(a[0]), "r"(a[1]), "r"(a[2]), "r"(a[3]), "r"(b[0]), "r"(b[1]));
}

__global__ void __launch_bounds__(NT, 3)
tsa_kernel(const float* __restrict__ q,
           const float* __restrict__ k1,
           const float* __restrict__ k2,
           const float* __restrict__ v1,
           const float* __restrict__ v2,
           float* __restrict__ out) {
    extern __shared__ __align__(1024) char smem[];
    const int tid = threadIdx.x;
    const int wid = tid >> 5, lane = tid & 31;
    const int wm = wid & 1;          // m-group: tiles {0,1,2} or {3,4}
    const int wn = wid >> 1;         // n-group: 2 n-tiles each
    const int nti = 3 - wm;          // m-tiles owned by this warp
    const int bid = blockIdx.x;
    const int h = bid & 3;
    const int s = (bid >> 2) & 2047;
    const int b = bid >> 13;
    const int amin = 64 - s;
    const uint32_t smb = smem_u32(smem);

    // ================= prologue =================
    const int qb = ((b * Sc + s) * Hc + h) * Dc;
    const int dq = tid & 15;
    float4 qv = *(const float4*)&q[qb + dq * 4];
    qv.x *= QSCALE; qv.y *= QSCALE; qv.z *= QSCALE; qv.w *= QSCALE;

    for (int i = tid; i < 65 * 16; i += NT) {
        int r = i >> 4;
        int g = s - 64 + r; if (g < 0) g = 0;
        int off = ((b * Sc + g) * Hc + h) * Dc + dq * 4;

        float4 kv = *(const float4*)&k1[off];
        kv.x *= qv.x; kv.y *= qv.y; kv.z *= qv.z; kv.w *= qv.w;
        {
            uint32_t h01, l01, h23, l23;
            split2(kv.x, kv.y, h01, l01);
            split2(kv.z, kv.w, h23, l23);
            *(uint2*)(smem + OFF_A3H + r * 144 + dq * 8) = make_uint2(h01, h23);
            *(uint2*)(smem + OFF_A3L + r * 144 + dq * 8) = make_uint2(l01, l23);
        }
        float4 cv = *(const float4*)&k2[off];
        if (r < 64) {
            uint32_t h01, l01, h23, l23;
            split2(cv.x, cv.y, h01, l01);
            split2(cv.z, cv.w, h23, l23);
            *(uint2*)(smem + OFF_B3H + r * 144 + dq * 8) = make_uint2(h01, h23);
            *(uint2*)(smem + OFF_B3L + r * 144 + dq * 8) = make_uint2(l01, l23);
        } else {
            *(float4*)(smem + OFF_K2R64 + dq * 16) = cv;
        }
        *(float4*)(smem + OFF_V1F + (r * 68 + dq * 4) * 4) = *(const float4*)&v1[off];
        float4 vv = *(const float4*)&v2[off];
        if (r < 64) {
            uint32_t h01, l01, h23, l23;
            split2(vv.x, vv.y, h01, l01);
            split2(vv.z, vv.w, h23, l23);
            *(uint2*)(smem + OFF_B4H + r * 144 + dq * 8) = make_uint2(h01, h23);
            *(uint2*)(smem + OFF_B4L + r * 144 + dq * 8) = make_uint2(l01, l23);
        } else {
            *(float4*)(smem + OFF_V2R64 + dq * 16) = vv;
        }
    }
    __syncthreads();

    // fragment addresses
    const int arow = (lane & 7) + 8 * ((lane >> 3) & 1);
    const int acol = 8 * (lane >> 4);
    const uint32_t aoffs = arow * 144 + acol * 2;          // + T*16*144 + k*32
    const uint32_t b3base = smb + OFF_B3H
        + ((wn * 2 + (lane >> 4)) * 8 + (lane & 7)) * 144
        + ((lane >> 3) & 1) * 16;                          // + k*32
    const uint32_t b4base = smb + OFF_B4H
        + (((lane >> 3) & 1) * 8 + (lane & 7)) * 144
        + (wn * 2 + (lane >> 4)) * 16;                     // + k*2304

    // ================= phase 3: scores via MMA (pre-scaled, log2 domain) =========
    float acc[3][2][4];
#pragma unroll
    for (int i = 0; i < 3; i++)
#pragma unroll
        for (int j = 0; j < 2; j++)
#pragma unroll
            for (int e = 0; e < 4; e++) acc[i][j][e] = 0.0f;

#pragma unroll
    for (int k = 0; k < 4; k++) {
        uint32_t bh[2][2], bl[2][2];
        ldsm4(bh[0][0], bh[0][1], bh[1][0], bh[1][1], b3base + k * 32);
        ldsm4(bl[0][0], bl[0][1], bl[1][0], bl[1][1], b3base + LD_B + k * 32);
#pragma unroll
        for (int i = 0; i < 3; i++) {
            if (i < nti) {
                uint32_t ah[4], al[4];
                uint32_t aa = smb + OFF_A3H + aoffs + (wm * 3 + i) * 16 * 144 + k * 32;
                ldsm4(ah[0], ah[1], ah[2], ah[3], aa);
                ldsm4(al[0], al[1], al[2], al[3], aa + LD_A);
#pragma unroll
                for (int j = 0; j < 2; j++) {
                    mma16816(acc[i][j], ah, bh[j]);
                    mma16816(acc[i][j], ah, bl[j]);
                    mma16816(acc[i][j], al, bh[j]);
                }
            }
        }
    }

    // ---- c = 64 score column (f32 SIMT, k1q reconstructed from bf16 tiles) ----
    float dloc = 0.0f;
    if (tid < 65) {
        const char* rowH = smem + OFF_A3H + tid * 144;
        const char* rowL = smem + OFF_A3L + tid * 144;
        const float* k2r = (const float*)(smem + OFF_K2R64);
        float a0 = 0.f, a1 = 0.f;
#pragma unroll
        for (int j = 0; j < 8; j++) {
            uint4 hh = *(const uint4*)(rowH + j * 16);
            uint4 ll = *(const uint4*)(rowL + j * 16);
            const float* kr = k2r + j * 8;
            a0 = fmaf(rlo(hh.x) + rlo(ll.x), kr[0], a0);
            a1 = fmaf(rhi(hh.x) + rhi(ll.x), kr[1], a1);
            a0 = fmaf(rlo(hh.y) + rlo(ll.y), kr[2], a0);
            a1 = fmaf(rhi(hh.y) + rhi(ll.y), kr[3], a1);
            a0 = fmaf(rlo(hh.z) + rlo(ll.z), kr[4], a0);
            a1 = fmaf(rhi(hh.z) + rhi(ll.z), kr[5], a1);
            a0 = fmaf(rlo(hh.w) + rlo(ll.w), kr[6], a0);
            a1 = fmaf(rhi(hh.w) + rhi(ll.w), kr[7], a1);
        }
        float w = (tid >= amin) ? exp2f(a0 + a1) : 0.0f;
        ((float*)(smem + OFF_WC64))[tid] = w;
        dloc += w;
    }
    __syncthreads();   // all warps done reading A3 (k1q) before W overwrites it

    // ================= epilogue A: mask+exp, W -> A-tile =================
    {
        const int rb = lane >> 2;
#pragma unroll
        for (int i = 0; i < 3; i++) {
            if (i < nti) {
                int r0 = (wm * 3 + i) * 16 + rb, r1 = r0 + 8;
                bool av0 = (r0 <= 64) && (r0 >= amin);
                bool av1 = (r1 <= 64) && (r1 >= amin);
#pragma unroll
                for (int j = 0; j < 2; j++) {
                    int c0 = (wn * 2 + j) * 8 + 2 * (lane & 3);
                    bool cv0 = (c0 >= amin), cv1 = (c0 + 1 >= amin);
                    float w0 = (av0 && cv0) ? exp2f(acc[i][j][0]) : 0.0f;
                    float w1 = (av0 && cv1) ? exp2f(acc[i][j][1]) : 0.0f;
                    float w2 = (av1 && cv0) ? exp2f(acc[i][j][2]) : 0.0f;
                    float w3 = (av1 && cv1) ? exp2f(acc[i][j][3]) : 0.0f;
                    dloc += (w0 + w1) + (w2 + w3);
                    if (r0 <= 64) {
                        uint32_t hh, ll;
                        split2(w0, w1, hh, ll);
                        *(uint32_t*)(smem + OFF_A3H + r0 * 144 + c0 * 2) = hh;
                        *(uint32_t*)(smem + OFF_A3L + r0 * 144 + c0 * 2) = ll;
                    }
                    if (r1 <= 64) {
                        uint32_t hh, ll;
                        split2(w2, w3, hh, ll);
                        *(uint32_t*)(smem + OFF_A3H + r1 * 144 + c0 * 2) = hh;
                        *(uint32_t*)(smem + OFF_A3L + r1 * 144 + c0 * 2) = ll;
                    }
                }
            }
        }
    }
#pragma unroll
    for (int o = 16; o; o >>= 1) dloc += __shfl_xor_sync(0xFFFFFFFFu, dloc, o);
    if (lane == 0) ((float*)(smem + OFF_DEN))[wid] = dloc;
    __syncthreads();   // W tile + WC64 + DEN visible

    // ================= phase 4: O = W @ V2 via MMA (trans B loads) =================
    float acc2[3][2][4];
#pragma unroll
    for (int i = 0; i < 3; i++)
#pragma unroll
        for (int j = 0; j < 2; j++)
#pragma unroll
            for (int e = 0; e < 4; e++) acc2[i][j][e] = 0.0f;

#pragma unroll
    for (int k = 0; k < 4; k++) {
        uint32_t bh[2][2], bl[2][2];
        ldsm4t(bh[0][0], bh[0][1], bh[1][0], bh[1][1], b4base + k * 2304);
        ldsm4t(bl[0][0], bl[0][1], bl[1][0], bl[1][1], b4base + LD_B + k * 2304);
#pragma unroll
        for (int i = 0; i < 3; i++) {
            if (i < nti) {
                uint32_t ah[4], al[4];
                uint32_t aa = smb + OFF_A3H + aoffs + (wm * 3 + i) * 16 * 144 + k * 32;
                ldsm4(ah[0], ah[1], ah[2], ah[3], aa);
                ldsm4(al[0], al[1], al[2], al[3], aa + LD_A);
#pragma unroll
                for (int j = 0; j < 2; j++) {
                    mma16816(acc2[i][j], ah, bh[j]);
                    mma16816(acc2[i][j], ah, bl[j]);
                    mma16816(acc2[i][j], al, bh[j]);
                }
            }
        }
    }

    // ================= epilogue B: +c64 term, v1 fold, a-reduce =================
    {
        const int res = lane >> 2;
        const float* WC = (const float*)(smem + OFF_WC64);
        const float* V2R = (const float*)(smem + OFF_V2R64);
        const float* V1F = (const float*)(smem + OFF_V1F);
#pragma unroll
        for (int j = 0; j < 2; j++) {
            int d0 = (wn * 2 + j) * 8 + 2 * (lane & 3);
            float vr0 = V2R[d0], vr1 = V2R[d0 + 1];
            float s0 = 0.0f, s1 = 0.0f;
#pragma unroll
            for (int i = 0; i < 3; i++) {
                if (i < nti) {
#pragma unroll
                    for (int hf = 0; hf < 2; hf++) {
                        int a = (wm * 3 + i) * 16 + res + 8 * hf;
                        if (a <= 64) {
                            float wc = WC[a];
                            float o0 = acc2[i][j][2 * hf + 0] + wc * vr0;
                            float o1 = acc2[i][j][2 * hf + 1] + wc * vr1;
                            s0 += o0 * V1F[a * 68 + d0];
                            s1 += o1 * V1F[a * 68 + d0 + 1];
                        }
                    }
                }
            }
            ((float*)(smem + OFF_OST))[(wm * 8 + res) * 68 + d0] = s0;
            ((float*)(smem + OFF_OST))[(wm * 8 + res) * 68 + d0 + 1] = s1;
        }
    }
    __syncthreads();

    if (tid < 64) {
        const float* DEN = (const float*)(smem + OFF_DEN);
        const float* OST = (const float*)(smem + OFF_OST);
        float den = 1e-8f;
#pragma unroll
        for (int w = 0; w < 8; w++) den += DEN[w];
        float num = 0.0f;
#pragma unroll
        for (int r = 0; r < 16; r++) num += OST[r * 68 + tid];
        out[qb + tid] = num / den;
    }
}

extern "C" void kernel_launch(void* const* d_in, const int* in_sizes, int n_in,
                              void* d_out, int out_size) {
    const float* q  = (const float*)d_in[0];
    const float* k1 = (const float*)d_in[1];
    const float* k2 = (const float*)d_in[2];
    const float* v1 = (const float*)d_in[3];
    const float* v2 = (const float*)d_in[4];
    float* out = (float*)d_out;

    cudaFuncSetAttribute(tsa_kernel, cudaFuncAttributeMaxDynamicSharedMemorySize,
                         SMEM_BYTES);
    dim3 grid(2 * Sc * Hc);
    tsa_kernel<<<grid, NT, SMEM_BYTES>>>(q, k1, k2, v1, v2, out);
}